// round 8
// baseline (speedup 1.0000x reference)
#include <cuda_runtime.h>
#include <cuda_bf16.h>
#include <cstdint>

// Problem constants
#define B_    64
#define T_    1024
#define D_    512
#define H_    512
#define O_    128
#define HALF_ 256
#define M_    (B_ * T_)          // 65536
#define BH_   (B_ * H_)          // 32768

// ---------------------------------------------------------------------------
// Device-global scratch
// ---------------------------------------------------------------------------
__device__ float          g_d1[T_ * B_ * H_];     // [T,B,H] fp32
__device__ float          g_d2[T_ * B_ * H_];     // [T,B,H] fp32
__device__ __nv_bfloat16  g_xh[M_ * D_];
__device__ __nv_bfloat16  g_xl[M_ * D_];
__device__ __nv_bfloat16  g_w1h[H_ * HALF_], g_w1l[H_ * HALF_];
__device__ __nv_bfloat16  g_w2h[H_ * HALF_], g_w2l[H_ * HALF_];
__device__ __nv_bfloat16  g_woh[O_ * H_],    g_wol[O_ * H_];
__device__ __nv_bfloat16  g_mh[T_ * B_ * H_];     // mems hi, row m = t*B+b
__device__ __nv_bfloat16  g_ml[T_ * B_ * H_];

// ---------------------------------------------------------------------------
// Helpers
// ---------------------------------------------------------------------------
__device__ __forceinline__ uint32_t smem_u32(const void* p) {
    uint32_t a;
    asm("{ .reg .u64 t; cvta.to.shared.u64 t, %1; cvt.u32.u64 %0, t; }"
        : "=r"(a) : "l"(p));
    return a;
}
__device__ __forceinline__ void ldsm4(uint32_t r[4], uint32_t addr) {
    asm volatile("ldmatrix.sync.aligned.m8n8.x4.shared.b16 {%0,%1,%2,%3}, [%4];"
        : "=r"(r[0]), "=r"(r[1]), "=r"(r[2]), "=r"(r[3]) : "r"(addr));
}
__device__ __forceinline__ void mma16816(float c[4], const uint32_t a[4],
                                         const uint32_t b0, const uint32_t b1) {
    asm volatile(
        "mma.sync.aligned.m16n8k16.row.col.f32.bf16.bf16.f32 "
        "{%0,%1,%2,%3}, {%4,%5,%6,%7}, {%8,%9}, {%0,%1,%2,%3};"
        : "+f"(c[0]), "+f"(c[1]), "+f"(c[2]), "+f"(c[3])
        : "r"(a[0]), "r"(a[1]), "r"(a[2]), "r"(a[3]), "r"(b0), "r"(b1));
}
__device__ __forceinline__ void cp16(uint32_t dst, const void* src) {
    asm volatile("cp.async.cg.shared.global [%0], [%1], 16;"
        :: "r"(dst), "l"(src) : "memory");
}
#define CP_COMMIT() asm volatile("cp.async.commit_group;" ::: "memory")
#define CP_WAIT0()  asm volatile("cp.async.wait_group 0;" ::: "memory")
#define CP_WAIT1()  asm volatile("cp.async.wait_group 1;" ::: "memory")
#define CP_WAIT2()  asm volatile("cp.async.wait_group 2;" ::: "memory")

// 64-byte rows (32 bf16), SW64 swizzle
#define SW64(o)   ((o) ^ (((o) >> 3) & 0x30))

// cp.async an R x 32 bf16 tile (K-major global) into SW64 smem. 512 threads.
template <int R>
__device__ __forceinline__ void cp_tile32(uint32_t sbase,
                                          const __nv_bfloat16* __restrict__ g,
                                          int ld, int row0, int k0, int tid)
{
    #pragma unroll
    for (int i = 0; i < (R * 4) / 512; ++i) {
        const int slot = tid + i * 512;
        const int r = slot >> 2;
        const int v = slot & 3;
        cp16(sbase + SW64((uint32_t)(r * 64 + v * 16)),
             g + (size_t)(row0 + r) * ld + k0 + v * 8);
    }
}

// ---------------------------------------------------------------------------
// Fused split: x, w1, w2, wo -> bf16 hi/lo planes, one launch.
// ---------------------------------------------------------------------------
#define NXV  ((M_ * D_) / 4)
#define NWV  ((H_ * HALF_) / 4)
#define NOV  ((O_ * H_) / 4)

__device__ __forceinline__ void split_vec(const float* src,
                                          __nv_bfloat16* hi, __nv_bfloat16* lo,
                                          int i)
{
    float4 v = ((const float4*)src)[i];
    float f[4] = {v.x, v.y, v.z, v.w};
    uint32_t ph[2], pl[2];
    #pragma unroll
    for (int j = 0; j < 2; ++j) {
        __nv_bfloat16 h0 = __float2bfloat16(f[2*j]);
        __nv_bfloat16 h1 = __float2bfloat16(f[2*j+1]);
        __nv_bfloat16 l0 = __float2bfloat16(f[2*j]   - __bfloat162float(h0));
        __nv_bfloat16 l1 = __float2bfloat16(f[2*j+1] - __bfloat162float(h1));
        ph[j] = (uint32_t)__bfloat16_as_ushort(h0) | ((uint32_t)__bfloat16_as_ushort(h1) << 16);
        pl[j] = (uint32_t)__bfloat16_as_ushort(l0) | ((uint32_t)__bfloat16_as_ushort(l1) << 16);
    }
    ((uint2*)hi)[i] = make_uint2(ph[0], ph[1]);
    ((uint2*)lo)[i] = make_uint2(pl[0], pl[1]);
}

__global__ void split_all_kernel(const float* __restrict__ x,
                                 const float* __restrict__ w1,
                                 const float* __restrict__ w2,
                                 const float* __restrict__ wo)
{
    const int total = NXV + 2 * NWV + NOV;
    for (int i = blockIdx.x * blockDim.x + threadIdx.x; i < total;
         i += gridDim.x * blockDim.x) {
        if (i < NXV)                  split_vec(x,  g_xh,  g_xl,  i);
        else if (i < NXV + NWV)       split_vec(w1, g_w1h, g_w1l, i - NXV);
        else if (i < NXV + 2 * NWV)   split_vec(w2, g_w2h, g_w2l, i - NXV - NWV);
        else                          split_vec(wo, g_woh, g_wol, i - NXV - 2 * NWV);
    }
}

// ---------------------------------------------------------------------------
// GEMM-1: CTA 128(m) x 256(n), K-chunk 32, 16 chunks (phase0: w1, phase1: w2),
// 4-stage cp.async multistage, one __syncthreads per chunk.
// 512 thr, 16 warps (4m x 4n), warp tile 32 x 64.
// ---------------------------------------------------------------------------
#define G1_OFF_AL 8192
#define G1_OFF_WH 16384
#define G1_OFF_WL 32768
#define G1_STAGE  49152
#define SMEM_G1   (1024 + 4 * G1_STAGE)

__global__ __launch_bounds__(512)
void hmma_gemm1_kernel()
{
    extern __shared__ __align__(16) char smraw[];
    char* smem = smraw + ((1024 - (smem_u32(smraw) & 1023)) & 1023);
    const uint32_t sbase = smem_u32(smem);

    const int tid    = threadIdx.x;
    const int wid    = tid >> 5;
    const int lane   = tid & 31;
    const int warp_m = (wid & 3) * 32;
    const int warp_n = (wid >> 2) * 64;

    const int m0 = blockIdx.x * 128;
    const int n0 = blockIdx.y * 256;

    auto issue_chunk = [&](int c) {
        const uint32_t sb = sbase + (c & 3) * G1_STAGE;
        const __nv_bfloat16* wh = (c >= 8) ? g_w2h : g_w1h;
        const __nv_bfloat16* wl = (c >= 8) ? g_w2l : g_w1l;
        const int kx = c * 32;
        const int kw = (c & 7) * 32;
        cp_tile32<128>(sb,             g_xh, D_,    m0, kx, tid);
        cp_tile32<128>(sb + G1_OFF_AL, g_xl, D_,    m0, kx, tid);
        cp_tile32<256>(sb + G1_OFF_WH, wh,   HALF_, n0, kw, tid);
        cp_tile32<256>(sb + G1_OFF_WL, wl,   HALF_, n0, kw, tid);
        CP_COMMIT();
    };

    float acc[2][8][4];
    #pragma unroll
    for (int a = 0; a < 2; ++a)
        #pragma unroll
        for (int b = 0; b < 8; ++b)
            #pragma unroll
            for (int cc = 0; cc < 4; ++cc) acc[a][b][cc] = 0.0f;

    issue_chunk(0);
    issue_chunk(1);
    issue_chunk(2);

    #pragma unroll 1
    for (int c = 0; c < 16; ++c) {
        if (c <= 13)      { CP_WAIT2(); }
        else if (c == 14) { CP_WAIT1(); }
        else              { CP_WAIT0(); }
        __syncthreads();

        if (c < 13) issue_chunk(c + 3);

        const uint32_t sb  = sbase + (c & 3) * G1_STAGE;
        const uint32_t sAh = sb, sAl = sb + G1_OFF_AL;
        const uint32_t sWh = sb + G1_OFF_WH, sWl = sb + G1_OFF_WL;

        #pragma unroll
        for (int ks = 0; ks < 2; ++ks) {
            const int akb = ks * 32 + ((lane & 16) ? 16 : 0);
            uint32_t ah[2][4], al[2][4];
            #pragma unroll
            for (int mt = 0; mt < 2; ++mt) {
                const int row = warp_m + mt * 16 + (lane & 15);
                const uint32_t off = SW64((uint32_t)(row * 64 + akb));
                ldsm4(ah[mt], sAh + off);
                ldsm4(al[mt], sAl + off);
            }
            const int bkb = ks * 32 + ((lane & 8) ? 16 : 0);
            #pragma unroll
            for (int nt2 = 0; nt2 < 4; ++nt2) {
                const int brow = warp_n + nt2 * 16 + (lane & 7) + ((lane & 16) ? 8 : 0);
                const uint32_t boff = SW64((uint32_t)(brow * 64 + bkb));
                uint32_t wh[4], wl[4];
                ldsm4(wh, sWh + boff);
                ldsm4(wl, sWl + boff);
                #pragma unroll
                for (int mt = 0; mt < 2; ++mt) {
                    mma16816(acc[mt][nt2 * 2 + 0], ah[mt], wh[0], wh[1]);
                    mma16816(acc[mt][nt2 * 2 + 1], ah[mt], wh[2], wh[3]);
                    mma16816(acc[mt][nt2 * 2 + 0], al[mt], wh[0], wh[1]);
                    mma16816(acc[mt][nt2 * 2 + 1], al[mt], wh[2], wh[3]);
                    mma16816(acc[mt][nt2 * 2 + 0], ah[mt], wl[0], wl[1]);
                    mma16816(acc[mt][nt2 * 2 + 1], ah[mt], wl[2], wl[3]);
                }
            }
        }

        if (c == 7 || c == 15) {
            float* dst = (c == 7) ? g_d1 : g_d2;
            #pragma unroll
            for (int mt = 0; mt < 2; ++mt) {
                #pragma unroll
                for (int half = 0; half < 2; ++half) {
                    const int m = m0 + warp_m + mt * 16 + (lane >> 2) + half * 8;
                    const int b = m >> 10;
                    const int t = m & (T_ - 1);
                    float* rowp = dst + (size_t)t * BH_ + (size_t)b * H_ + n0 + warp_n;
                    #pragma unroll
                    for (int nt = 0; nt < 8; ++nt) {
                        const int n = nt * 8 + (lane & 3) * 2;
                        float2 v = half ? make_float2(acc[mt][nt][2], acc[mt][nt][3])
                                        : make_float2(acc[mt][nt][0], acc[mt][nt][1]);
                        *(float2*)(rowp + n) = v;
                    }
                }
            }
            #pragma unroll
            for (int a = 0; a < 2; ++a)
                #pragma unroll
                for (int b = 0; b < 8; ++b)
                    #pragma unroll
                    for (int cc = 0; cc < 4; ++cc) acc[a][b][cc] = 0.0f;
        }
    }
}

// ---------------------------------------------------------------------------
// Scan: sequential EMA over T; emits mems as bf16 hi/lo split.
// ---------------------------------------------------------------------------
__global__ __launch_bounds__(256)
void scan_kernel(const float* __restrict__ b1, const float* __restrict__ tau1,
                 const float* __restrict__ b2, const float* __restrict__ tau2)
{
    const int idx = blockIdx.x * blockDim.x + threadIdx.x;   // 0..32767
    const int h   = idx & (H_ - 1);

    const float a1 = 1.0f / (1.0f + __expf(-tau1[h]));
    const float a2 = 1.0f / (1.0f + __expf(-tau2[h]));
    const float c1 = 1.0f - a1;
    const float c2 = 1.0f - a2;
    const float bb1 = b1[h];
    const float bb2 = b2[h];

    float d1 = 0.0f, d2 = 0.0f, mem = 0.0f;

    #pragma unroll 1
    for (int t = 0; t < T_; t += 8) {
        float i1[8], i2[8];
        #pragma unroll
        for (int u = 0; u < 8; ++u) {
            i1[u] = g_d1[(size_t)(t + u) * BH_ + idx];
            i2[u] = g_d2[(size_t)(t + u) * BH_ + idx];
        }
        #pragma unroll
        for (int u = 0; u < 8; ++u) {
            d1  = a1 * d1 + c1 * (i1[u] + bb1);
            d2  = a2 * d2 + c2 * (i2[u] + bb2);
            mem = 0.8f * mem + 0.2f * (d1 + d2);
            const size_t off = (size_t)(t + u) * BH_ + idx;
            __nv_bfloat16 mh = __float2bfloat16(mem);
            __nv_bfloat16 ml = __float2bfloat16(mem - __bfloat162float(mh));
            g_mh[off] = mh;
            g_ml[off] = ml;
        }
    }
}

// ---------------------------------------------------------------------------
// GEMM-2: out = sigmoid(mems @ wo^T + bo). CTA 128 x 128, K-chunk 32,
// 16 chunks, 4-stage multistage. 512 thr, warp 32 x 32.
// ---------------------------------------------------------------------------
#define G2_OFF_AL 8192
#define G2_OFF_WH 16384
#define G2_OFF_WL 24576
#define G2_STAGE  32768
#define SMEM_G2   (1024 + 4 * G2_STAGE)

__global__ __launch_bounds__(512)
void hmma_gemm2_kernel(const float* __restrict__ bo, float* __restrict__ out)
{
    extern __shared__ __align__(16) char smraw[];
    char* smem = smraw + ((1024 - (smem_u32(smraw) & 1023)) & 1023);
    const uint32_t sbase = smem_u32(smem);

    const int tid    = threadIdx.x;
    const int wid    = tid >> 5;
    const int lane   = tid & 31;
    const int warp_m = (wid & 3) * 32;
    const int warp_n = (wid >> 2) * 32;

    const int m0 = blockIdx.x * 128;

    auto issue_chunk = [&](int c) {
        const uint32_t sb = sbase + (c & 3) * G2_STAGE;
        const int k1 = c * 32;
        cp_tile32<128>(sb,             g_mh,  H_, m0, k1, tid);
        cp_tile32<128>(sb + G2_OFF_AL, g_ml,  H_, m0, k1, tid);
        cp_tile32<128>(sb + G2_OFF_WH, g_woh, H_, 0,  k1, tid);
        cp_tile32<128>(sb + G2_OFF_WL, g_wol, H_, 0,  k1, tid);
        CP_COMMIT();
    };

    float acc[2][4][4];
    #pragma unroll
    for (int a = 0; a < 2; ++a)
        #pragma unroll
        for (int b = 0; b < 4; ++b)
            #pragma unroll
            for (int c = 0; c < 4; ++c) acc[a][b][c] = 0.0f;

    issue_chunk(0);
    issue_chunk(1);
    issue_chunk(2);

    #pragma unroll 1
    for (int c = 0; c < 16; ++c) {
        if (c <= 13)      { CP_WAIT2(); }
        else if (c == 14) { CP_WAIT1(); }
        else              { CP_WAIT0(); }
        __syncthreads();

        if (c < 13) issue_chunk(c + 3);

        const uint32_t sb  = sbase + (c & 3) * G2_STAGE;
        const uint32_t sAh = sb, sAl = sb + G2_OFF_AL;
        const uint32_t sWh = sb + G2_OFF_WH, sWl = sb + G2_OFF_WL;

        #pragma unroll
        for (int ks = 0; ks < 2; ++ks) {
            const int akb = ks * 32 + ((lane & 16) ? 16 : 0);
            uint32_t ah[2][4], al[2][4];
            #pragma unroll
            for (int mt = 0; mt < 2; ++mt) {
                const int row = warp_m + mt * 16 + (lane & 15);
                const uint32_t off = SW64((uint32_t)(row * 64 + akb));
                ldsm4(ah[mt], sAh + off);
                ldsm4(al[mt], sAl + off);
            }
            const int bkb = ks * 32 + ((lane & 8) ? 16 : 0);
            #pragma unroll
            for (int nt2 = 0; nt2 < 2; ++nt2) {
                const int brow = warp_n + nt2 * 16 + (lane & 7) + ((lane & 16) ? 8 : 0);
                const uint32_t boff = SW64((uint32_t)(brow * 64 + bkb));
                uint32_t wh[4], wl[4];
                ldsm4(wh, sWh + boff);
                ldsm4(wl, sWl + boff);
                #pragma unroll
                for (int mt = 0; mt < 2; ++mt) {
                    mma16816(acc[mt][nt2 * 2 + 0], ah[mt], wh[0], wh[1]);
                    mma16816(acc[mt][nt2 * 2 + 1], ah[mt], wh[2], wh[3]);
                    mma16816(acc[mt][nt2 * 2 + 0], al[mt], wh[0], wh[1]);
                    mma16816(acc[mt][nt2 * 2 + 1], al[mt], wh[2], wh[3]);
                    mma16816(acc[mt][nt2 * 2 + 0], ah[mt], wl[0], wl[1]);
                    mma16816(acc[mt][nt2 * 2 + 1], ah[mt], wl[2], wl[3]);
                }
            }
        }
    }

    // Epilogue: bias + sigmoid; out[b,t,o], row m = t*B + b
    #pragma unroll
    for (int mt = 0; mt < 2; ++mt) {
        #pragma unroll
        for (int half = 0; half < 2; ++half) {
            const int m = m0 + warp_m + mt * 16 + (lane >> 2) + half * 8;
            const int t = m >> 6;           // / B_
            const int b = m & (B_ - 1);
            float* rowp = out + (size_t)b * (T_ * O_) + (size_t)t * O_ + warp_n;
            #pragma unroll
            for (int nt = 0; nt < 4; ++nt) {
                const int n = nt * 8 + (lane & 3) * 2;
                float v0 = half ? acc[mt][nt][2] : acc[mt][nt][0];
                float v1 = half ? acc[mt][nt][3] : acc[mt][nt][1];
                v0 += bo[warp_n + n];
                v1 += bo[warp_n + n + 1];
                v0 = 1.0f / (1.0f + __expf(-v0));
                v1 = 1.0f / (1.0f + __expf(-v1));
                *(float2*)(rowp + n) = make_float2(v0, v1);
            }
        }
    }
}

// ---------------------------------------------------------------------------
extern "C" void kernel_launch(void* const* d_in, const int* in_sizes, int n_in,
                              void* d_out, int out_size)
{
    const float* x    = (const float*)d_in[0];
    const float* w1   = (const float*)d_in[1];
    const float* b1   = (const float*)d_in[2];
    const float* tau1 = (const float*)d_in[3];
    const float* w2   = (const float*)d_in[4];
    const float* b2   = (const float*)d_in[5];
    const float* tau2 = (const float*)d_in[6];
    const float* wo   = (const float*)d_in[7];
    const float* bo   = (const float*)d_in[8];
    float* out = (float*)d_out;

    cudaFuncSetAttribute(hmma_gemm1_kernel,
                         cudaFuncAttributeMaxDynamicSharedMemorySize, SMEM_G1);
    cudaFuncSetAttribute(hmma_gemm2_kernel,
                         cudaFuncAttributeMaxDynamicSharedMemorySize, SMEM_G2);

    split_all_kernel<<<2048, 256>>>(x, w1, w2, wo);

    dim3 g1(M_ / 128, H_ / 256);          // 512 x 2
    hmma_gemm1_kernel<<<g1, 512, SMEM_G1>>>();

    scan_kernel<<<BH_ / 256, 256>>>(b1, tau1, b2, tau2);

    hmma_gemm2_kernel<<<M_ / 128, 512, SMEM_G2>>>(bo, out);
}

// round 9
// speedup vs baseline: 1.0328x; 1.0328x over previous
#include <cuda_runtime.h>
#include <cuda_bf16.h>
#include <cstdint>

// Problem constants
#define B_    64
#define T_    1024
#define D_    512
#define H_    512
#define O_    128
#define HALF_ 256
#define M_    (B_ * T_)          // 65536
#define BH_   (B_ * H_)          // 32768

// ---------------------------------------------------------------------------
// Device-global scratch
// ---------------------------------------------------------------------------
__device__ float          g_d1[T_ * B_ * H_];     // [T,B,H] fp32
__device__ float          g_d2[T_ * B_ * H_];     // [T,B,H] fp32
__device__ __nv_bfloat16  g_xh[M_ * D_];
__device__ __nv_bfloat16  g_xl[M_ * D_];
__device__ __nv_bfloat16  g_w1h[H_ * HALF_], g_w1l[H_ * HALF_];
__device__ __nv_bfloat16  g_w2h[H_ * HALF_], g_w2l[H_ * HALF_];
__device__ __nv_bfloat16  g_woh[O_ * H_],    g_wol[O_ * H_];
__device__ __nv_bfloat16  g_mh[T_ * B_ * H_];     // mems hi, row m = t*B+b
__device__ __nv_bfloat16  g_ml[T_ * B_ * H_];

// ---------------------------------------------------------------------------
// Helpers
// ---------------------------------------------------------------------------
__device__ __forceinline__ uint32_t smem_u32(const void* p) {
    uint32_t a;
    asm("{ .reg .u64 t; cvta.to.shared.u64 t, %1; cvt.u32.u64 %0, t; }"
        : "=r"(a) : "l"(p));
    return a;
}
__device__ __forceinline__ void ldsm4(uint32_t r[4], uint32_t addr) {
    asm volatile("ldmatrix.sync.aligned.m8n8.x4.shared.b16 {%0,%1,%2,%3}, [%4];"
        : "=r"(r[0]), "=r"(r[1]), "=r"(r[2]), "=r"(r[3]) : "r"(addr));
}
__device__ __forceinline__ void mma16816(float c[4], const uint32_t a[4],
                                         const uint32_t b0, const uint32_t b1) {
    asm volatile(
        "mma.sync.aligned.m16n8k16.row.col.f32.bf16.bf16.f32 "
        "{%0,%1,%2,%3}, {%4,%5,%6,%7}, {%8,%9}, {%0,%1,%2,%3};"
        : "+f"(c[0]), "+f"(c[1]), "+f"(c[2]), "+f"(c[3])
        : "r"(a[0]), "r"(a[1]), "r"(a[2]), "r"(a[3]), "r"(b0), "r"(b1));
}
__device__ __forceinline__ void cp16(uint32_t dst, const void* src) {
    asm volatile("cp.async.cg.shared.global [%0], [%1], 16;"
        :: "r"(dst), "l"(src) : "memory");
}
#define CP_COMMIT() asm volatile("cp.async.commit_group;" ::: "memory")
#define CP_WAIT0()  asm volatile("cp.async.wait_group 0;" ::: "memory")
#define CP_WAIT1()  asm volatile("cp.async.wait_group 1;" ::: "memory")

// 64-byte rows (32 bf16), SW64 swizzle
#define SW64(o)   ((o) ^ (((o) >> 3) & 0x30))

// cp.async an R x 32 bf16 tile (K-major global) into SW64 smem. 256 threads.
template <int R>
__device__ __forceinline__ void cp_tile32(uint32_t sbase,
                                          const __nv_bfloat16* __restrict__ g,
                                          int ld, int row0, int k0, int tid)
{
    #pragma unroll
    for (int i = 0; i < (R * 4) / 256; ++i) {
        const int slot = tid + i * 256;
        const int r = slot >> 2;
        const int v = slot & 3;
        cp16(sbase + SW64((uint32_t)(r * 64 + v * 16)),
             g + (size_t)(row0 + r) * ld + k0 + v * 8);
    }
}

// ---------------------------------------------------------------------------
// Fused split: x, w1, w2, wo -> bf16 hi/lo planes, one launch.
// ---------------------------------------------------------------------------
#define NXV  ((M_ * D_) / 4)
#define NWV  ((H_ * HALF_) / 4)
#define NOV  ((O_ * H_) / 4)

__device__ __forceinline__ void split_vec(const float* src,
                                          __nv_bfloat16* hi, __nv_bfloat16* lo,
                                          int i)
{
    float4 v = ((const float4*)src)[i];
    float f[4] = {v.x, v.y, v.z, v.w};
    uint32_t ph[2], pl[2];
    #pragma unroll
    for (int j = 0; j < 2; ++j) {
        __nv_bfloat16 h0 = __float2bfloat16(f[2*j]);
        __nv_bfloat16 h1 = __float2bfloat16(f[2*j+1]);
        __nv_bfloat16 l0 = __float2bfloat16(f[2*j]   - __bfloat162float(h0));
        __nv_bfloat16 l1 = __float2bfloat16(f[2*j+1] - __bfloat162float(h1));
        ph[j] = (uint32_t)__bfloat16_as_ushort(h0) | ((uint32_t)__bfloat16_as_ushort(h1) << 16);
        pl[j] = (uint32_t)__bfloat16_as_ushort(l0) | ((uint32_t)__bfloat16_as_ushort(l1) << 16);
    }
    ((uint2*)hi)[i] = make_uint2(ph[0], ph[1]);
    ((uint2*)lo)[i] = make_uint2(pl[0], pl[1]);
}

__global__ void split_all_kernel(const float* __restrict__ x,
                                 const float* __restrict__ w1,
                                 const float* __restrict__ w2,
                                 const float* __restrict__ wo)
{
    const int total = NXV + 2 * NWV + NOV;
    for (int i = blockIdx.x * blockDim.x + threadIdx.x; i < total;
         i += gridDim.x * blockDim.x) {
        if (i < NXV)                  split_vec(x,  g_xh,  g_xl,  i);
        else if (i < NXV + NWV)       split_vec(w1, g_w1h, g_w1l, i - NXV);
        else if (i < NXV + 2 * NWV)   split_vec(w2, g_w2h, g_w2l, i - NXV - NWV);
        else                          split_vec(wo, g_woh, g_wol, i - NXV - 2 * NWV);
    }
}

// ---------------------------------------------------------------------------
// Shared GEMM geometry: CTA 128(m) x 128(n), 256 thr, 8 warps (4m x 2n),
// warp tile 32 x 64, K-chunk 32, 3-stage cp.async multistage, 2 CTAs/SM.
// Stage: Ah|Al|Wh|Wl, each 128x32 bf16 = 8 KB -> 32 KB/stage, 96 KB total.
// ---------------------------------------------------------------------------
#define OFF_AL  8192
#define OFF_WH  16384
#define OFF_WL  24576
#define STAGE_B 32768
#define SMEM_GEMM (1024 + 3 * STAGE_B)

// 3-term compute of one K32 chunk for warp tile 32x64.
__device__ __forceinline__ void chunk_compute(uint32_t sb, int warp_m, int warp_n,
                                              int lane, float acc[2][8][4])
{
    const uint32_t sAh = sb, sAl = sb + OFF_AL;
    const uint32_t sWh = sb + OFF_WH, sWl = sb + OFF_WL;
    #pragma unroll
    for (int ks = 0; ks < 2; ++ks) {
        const int akb = ks * 32 + ((lane & 16) ? 16 : 0);
        uint32_t ah[2][4], al[2][4];
        #pragma unroll
        for (int mt = 0; mt < 2; ++mt) {
            const int row = warp_m + mt * 16 + (lane & 15);
            const uint32_t off = SW64((uint32_t)(row * 64 + akb));
            ldsm4(ah[mt], sAh + off);
            ldsm4(al[mt], sAl + off);
        }
        const int bkb = ks * 32 + ((lane & 8) ? 16 : 0);
        #pragma unroll
        for (int nt2 = 0; nt2 < 4; ++nt2) {
            const int brow = warp_n + nt2 * 16 + (lane & 7) + ((lane & 16) ? 8 : 0);
            const uint32_t boff = SW64((uint32_t)(brow * 64 + bkb));
            uint32_t wh[4], wl[4];
            ldsm4(wh, sWh + boff);
            ldsm4(wl, sWl + boff);
            #pragma unroll
            for (int mt = 0; mt < 2; ++mt) {
                mma16816(acc[mt][nt2 * 2 + 0], ah[mt], wh[0], wh[1]);
                mma16816(acc[mt][nt2 * 2 + 1], ah[mt], wh[2], wh[3]);
                mma16816(acc[mt][nt2 * 2 + 0], al[mt], wh[0], wh[1]);
                mma16816(acc[mt][nt2 * 2 + 1], al[mt], wh[2], wh[3]);
                mma16816(acc[mt][nt2 * 2 + 0], ah[mt], wl[0], wl[1]);
                mma16816(acc[mt][nt2 * 2 + 1], ah[mt], wl[2], wl[3]);
            }
        }
    }
}

__device__ __forceinline__ void acc_zero(float acc[2][8][4]) {
    #pragma unroll
    for (int a = 0; a < 2; ++a)
        #pragma unroll
        for (int b = 0; b < 8; ++b)
            #pragma unroll
            for (int c = 0; c < 4; ++c) acc[a][b][c] = 0.0f;
}

// ---------------------------------------------------------------------------
// GEMM-1: 16 K32 chunks (0-7: x[:256]@w1, 8-15: x[256:]@w2). Grid (512, 4).
// ---------------------------------------------------------------------------
__global__ __launch_bounds__(256, 2)
void hmma_gemm1_kernel()
{
    extern __shared__ __align__(16) char smraw[];
    char* smem = smraw + ((1024 - (smem_u32(smraw) & 1023)) & 1023);
    const uint32_t sbase = smem_u32(smem);

    const int tid    = threadIdx.x;
    const int wid    = tid >> 5;
    const int lane   = tid & 31;
    const int warp_m = (wid & 3) * 32;
    const int warp_n = (wid >> 2) * 64;

    const int m0 = blockIdx.x * 128;
    const int n0 = blockIdx.y * 128;

    auto issue_chunk = [&](int c) {
        const uint32_t sb = sbase + (c % 3) * STAGE_B;
        const __nv_bfloat16* wh = (c >= 8) ? g_w2h : g_w1h;
        const __nv_bfloat16* wl = (c >= 8) ? g_w2l : g_w1l;
        const int kx = c * 32;
        const int kw = (c & 7) * 32;
        cp_tile32<128>(sb,          g_xh, D_,    m0, kx, tid);
        cp_tile32<128>(sb + OFF_AL, g_xl, D_,    m0, kx, tid);
        cp_tile32<128>(sb + OFF_WH, wh,   HALF_, n0, kw, tid);
        cp_tile32<128>(sb + OFF_WL, wl,   HALF_, n0, kw, tid);
        CP_COMMIT();
    };

    float acc[2][8][4];
    acc_zero(acc);

    issue_chunk(0);
    issue_chunk(1);

    #pragma unroll 1
    for (int c = 0; c < 16; ++c) {
        if (c < 15) { CP_WAIT1(); } else { CP_WAIT0(); }
        __syncthreads();
        if (c + 2 < 16) issue_chunk(c + 2);

        chunk_compute(sbase + (c % 3) * STAGE_B, warp_m, warp_n, lane, acc);

        if (c == 7 || c == 15) {
            float* dst = (c == 7) ? g_d1 : g_d2;
            #pragma unroll
            for (int mt = 0; mt < 2; ++mt) {
                #pragma unroll
                for (int half = 0; half < 2; ++half) {
                    const int m = m0 + warp_m + mt * 16 + (lane >> 2) + half * 8;
                    const int b = m >> 10;
                    const int t = m & (T_ - 1);
                    float* rowp = dst + (size_t)t * BH_ + (size_t)b * H_ + n0 + warp_n;
                    #pragma unroll
                    for (int nt = 0; nt < 8; ++nt) {
                        const int n = nt * 8 + (lane & 3) * 2;
                        float2 v = half ? make_float2(acc[mt][nt][2], acc[mt][nt][3])
                                        : make_float2(acc[mt][nt][0], acc[mt][nt][1]);
                        *(float2*)(rowp + n) = v;
                    }
                }
            }
            acc_zero(acc);
        }
    }
}

// ---------------------------------------------------------------------------
// Scan: sequential EMA over T; emits mems as bf16 hi/lo split.
// ---------------------------------------------------------------------------
__global__ __launch_bounds__(256)
void scan_kernel(const float* __restrict__ b1, const float* __restrict__ tau1,
                 const float* __restrict__ b2, const float* __restrict__ tau2)
{
    const int idx = blockIdx.x * blockDim.x + threadIdx.x;   // 0..32767
    const int h   = idx & (H_ - 1);

    const float a1 = 1.0f / (1.0f + __expf(-tau1[h]));
    const float a2 = 1.0f / (1.0f + __expf(-tau2[h]));
    const float c1 = 1.0f - a1;
    const float c2 = 1.0f - a2;
    const float bb1 = b1[h];
    const float bb2 = b2[h];

    float d1 = 0.0f, d2 = 0.0f, mem = 0.0f;

    #pragma unroll 1
    for (int t = 0; t < T_; t += 8) {
        float i1[8], i2[8];
        #pragma unroll
        for (int u = 0; u < 8; ++u) {
            i1[u] = g_d1[(size_t)(t + u) * BH_ + idx];
            i2[u] = g_d2[(size_t)(t + u) * BH_ + idx];
        }
        #pragma unroll
        for (int u = 0; u < 8; ++u) {
            d1  = a1 * d1 + c1 * (i1[u] + bb1);
            d2  = a2 * d2 + c2 * (i2[u] + bb2);
            mem = 0.8f * mem + 0.2f * (d1 + d2);
            const size_t off = (size_t)(t + u) * BH_ + idx;
            __nv_bfloat16 mh = __float2bfloat16(mem);
            __nv_bfloat16 ml = __float2bfloat16(mem - __bfloat162float(mh));
            g_mh[off] = mh;
            g_ml[off] = ml;
        }
    }
}

// ---------------------------------------------------------------------------
// GEMM-2: out = sigmoid(mems @ wo^T + bo). 16 K32 chunks. Grid (512).
// ---------------------------------------------------------------------------
__global__ __launch_bounds__(256, 2)
void hmma_gemm2_kernel(const float* __restrict__ bo, float* __restrict__ out)
{
    extern __shared__ __align__(16) char smraw[];
    char* smem = smraw + ((1024 - (smem_u32(smraw) & 1023)) & 1023);
    const uint32_t sbase = smem_u32(smem);

    const int tid    = threadIdx.x;
    const int wid    = tid >> 5;
    const int lane   = tid & 31;
    const int warp_m = (wid & 3) * 32;
    const int warp_n = (wid >> 2) * 64;

    const int m0 = blockIdx.x * 128;

    auto issue_chunk = [&](int c) {
        const uint32_t sb = sbase + (c % 3) * STAGE_B;
        const int k1 = c * 32;
        cp_tile32<128>(sb,          g_mh,  H_, m0, k1, tid);
        cp_tile32<128>(sb + OFF_AL, g_ml,  H_, m0, k1, tid);
        cp_tile32<128>(sb + OFF_WH, g_woh, H_, 0,  k1, tid);
        cp_tile32<128>(sb + OFF_WL, g_wol, H_, 0,  k1, tid);
        CP_COMMIT();
    };

    float acc[2][8][4];
    acc_zero(acc);

    issue_chunk(0);
    issue_chunk(1);

    #pragma unroll 1
    for (int c = 0; c < 16; ++c) {
        if (c < 15) { CP_WAIT1(); } else { CP_WAIT0(); }
        __syncthreads();
        if (c + 2 < 16) issue_chunk(c + 2);

        chunk_compute(sbase + (c % 3) * STAGE_B, warp_m, warp_n, lane, acc);
    }

    // Epilogue: bias + sigmoid; out[b,t,o], row m = t*B + b
    #pragma unroll
    for (int mt = 0; mt < 2; ++mt) {
        #pragma unroll
        for (int half = 0; half < 2; ++half) {
            const int m = m0 + warp_m + mt * 16 + (lane >> 2) + half * 8;
            const int t = m >> 6;           // / B_
            const int b = m & (B_ - 1);
            float* rowp = out + (size_t)b * (T_ * O_) + (size_t)t * O_ + warp_n;
            #pragma unroll
            for (int nt = 0; nt < 8; ++nt) {
                const int n = nt * 8 + (lane & 3) * 2;
                float v0 = half ? acc[mt][nt][2] : acc[mt][nt][0];
                float v1 = half ? acc[mt][nt][3] : acc[mt][nt][1];
                v0 += bo[warp_n + n];
                v1 += bo[warp_n + n + 1];
                v0 = 1.0f / (1.0f + __expf(-v0));
                v1 = 1.0f / (1.0f + __expf(-v1));
                *(float2*)(rowp + n) = make_float2(v0, v1);
            }
        }
    }
}

// ---------------------------------------------------------------------------
extern "C" void kernel_launch(void* const* d_in, const int* in_sizes, int n_in,
                              void* d_out, int out_size)
{
    const float* x    = (const float*)d_in[0];
    const float* w1   = (const float*)d_in[1];
    const float* b1   = (const float*)d_in[2];
    const float* tau1 = (const float*)d_in[3];
    const float* w2   = (const float*)d_in[4];
    const float* b2   = (const float*)d_in[5];
    const float* tau2 = (const float*)d_in[6];
    const float* wo   = (const float*)d_in[7];
    const float* bo   = (const float*)d_in[8];
    float* out = (float*)d_out;

    cudaFuncSetAttribute(hmma_gemm1_kernel,
                         cudaFuncAttributeMaxDynamicSharedMemorySize, SMEM_GEMM);
    cudaFuncSetAttribute(hmma_gemm2_kernel,
                         cudaFuncAttributeMaxDynamicSharedMemorySize, SMEM_GEMM);

    split_all_kernel<<<2048, 256>>>(x, w1, w2, wo);

    dim3 g1(M_ / 128, H_ / 128);          // 512 x 4
    hmma_gemm1_kernel<<<g1, 256, SMEM_GEMM>>>();

    scan_kernel<<<BH_ / 256, 256>>>(b1, tau1, b2, tau2);

    hmma_gemm2_kernel<<<M_ / 128, 256, SMEM_GEMM>>>(bo, out);
}

// round 10
// speedup vs baseline: 1.0516x; 1.0182x over previous
#include <cuda_runtime.h>
#include <cuda_bf16.h>
#include <cstdint>

// Problem constants
#define B_    64
#define T_    1024
#define D_    512
#define H_    512
#define O_    128
#define HALF_ 256
#define M_    (B_ * T_)          // 65536
#define BH_   (B_ * H_)          // 32768

// ---------------------------------------------------------------------------
// Device-global scratch
// ---------------------------------------------------------------------------
__device__ float          g_d1[T_ * B_ * H_];     // [T,B,H] fp32
__device__ float          g_d2[T_ * B_ * H_];     // [T,B,H] fp32
__device__ __nv_bfloat16  g_xh[M_ * D_];
__device__ __nv_bfloat16  g_xl[M_ * D_];
__device__ __nv_bfloat16  g_w1h[H_ * HALF_], g_w1l[H_ * HALF_];
__device__ __nv_bfloat16  g_w2h[H_ * HALF_], g_w2l[H_ * HALF_];
__device__ __nv_bfloat16  g_woh[O_ * H_],    g_wol[O_ * H_];
__device__ __nv_bfloat16  g_mh[T_ * B_ * H_];     // mems hi, row m = t*B+b
__device__ __nv_bfloat16  g_ml[T_ * B_ * H_];

// ---------------------------------------------------------------------------
// Helpers
// ---------------------------------------------------------------------------
__device__ __forceinline__ uint32_t smem_u32(const void* p) {
    uint32_t a;
    asm("{ .reg .u64 t; cvta.to.shared.u64 t, %1; cvt.u32.u64 %0, t; }"
        : "=r"(a) : "l"(p));
    return a;
}
__device__ __forceinline__ void ldsm4(uint32_t r[4], uint32_t addr) {
    asm volatile("ldmatrix.sync.aligned.m8n8.x4.shared.b16 {%0,%1,%2,%3}, [%4];"
        : "=r"(r[0]), "=r"(r[1]), "=r"(r[2]), "=r"(r[3]) : "r"(addr));
}
__device__ __forceinline__ void mma16816(float c[4], const uint32_t a[4],
                                         const uint32_t b0, const uint32_t b1) {
    asm volatile(
        "mma.sync.aligned.m16n8k16.row.col.f32.bf16.bf16.f32 "
        "{%0,%1,%2,%3}, {%4,%5,%6,%7}, {%8,%9}, {%0,%1,%2,%3};"
        : "+f"(c[0]), "+f"(c[1]), "+f"(c[2]), "+f"(c[3])
        : "r"(a[0]), "r"(a[1]), "r"(a[2]), "r"(a[3]), "r"(b0), "r"(b1));
}
__device__ __forceinline__ void cp16(uint32_t dst, const void* src) {
    asm volatile("cp.async.cg.shared.global [%0], [%1], 16;"
        :: "r"(dst), "l"(src) : "memory");
}
#define CP_COMMIT() asm volatile("cp.async.commit_group;" ::: "memory")
#define CP_WAIT0()  asm volatile("cp.async.wait_group 0;" ::: "memory")
#define CP_WAIT1()  asm volatile("cp.async.wait_group 1;" ::: "memory")

// 64-byte rows (32 bf16), SW64 swizzle
#define SW64(o)   ((o) ^ (((o) >> 3) & 0x30))

// cp.async an R x 32 bf16 tile (K-major global) into SW64 smem. 256 threads.
template <int R>
__device__ __forceinline__ void cp_tile32(uint32_t sbase,
                                          const __nv_bfloat16* __restrict__ g,
                                          int ld, int row0, int k0, int tid)
{
    #pragma unroll
    for (int i = 0; i < (R * 4) / 256; ++i) {
        const int slot = tid + i * 256;
        const int r = slot >> 2;
        const int v = slot & 3;
        cp16(sbase + SW64((uint32_t)(r * 64 + v * 16)),
             g + (size_t)(row0 + r) * ld + k0 + v * 8);
    }
}

// ---------------------------------------------------------------------------
// Fused split: x, w1, w2, wo -> bf16 hi/lo planes, one launch.
// ---------------------------------------------------------------------------
#define NXV  ((M_ * D_) / 4)
#define NWV  ((H_ * HALF_) / 4)
#define NOV  ((O_ * H_) / 4)

__device__ __forceinline__ void split_vec(const float* src,
                                          __nv_bfloat16* hi, __nv_bfloat16* lo,
                                          int i)
{
    float4 v = ((const float4*)src)[i];
    float f[4] = {v.x, v.y, v.z, v.w};
    uint32_t ph[2], pl[2];
    #pragma unroll
    for (int j = 0; j < 2; ++j) {
        __nv_bfloat16 h0 = __float2bfloat16(f[2*j]);
        __nv_bfloat16 h1 = __float2bfloat16(f[2*j+1]);
        __nv_bfloat16 l0 = __float2bfloat16(f[2*j]   - __bfloat162float(h0));
        __nv_bfloat16 l1 = __float2bfloat16(f[2*j+1] - __bfloat162float(h1));
        ph[j] = (uint32_t)__bfloat16_as_ushort(h0) | ((uint32_t)__bfloat16_as_ushort(h1) << 16);
        pl[j] = (uint32_t)__bfloat16_as_ushort(l0) | ((uint32_t)__bfloat16_as_ushort(l1) << 16);
    }
    ((uint2*)hi)[i] = make_uint2(ph[0], ph[1]);
    ((uint2*)lo)[i] = make_uint2(pl[0], pl[1]);
}

__global__ void split_all_kernel(const float* __restrict__ x,
                                 const float* __restrict__ w1,
                                 const float* __restrict__ w2,
                                 const float* __restrict__ wo)
{
    const int total = NXV + 2 * NWV + NOV;
    for (int i = blockIdx.x * blockDim.x + threadIdx.x; i < total;
         i += gridDim.x * blockDim.x) {
        if (i < NXV)                  split_vec(x,  g_xh,  g_xl,  i);
        else if (i < NXV + NWV)       split_vec(w1, g_w1h, g_w1l, i - NXV);
        else if (i < NXV + 2 * NWV)   split_vec(w2, g_w2h, g_w2l, i - NXV - NWV);
        else                          split_vec(wo, g_woh, g_wol, i - NXV - 2 * NWV);
    }
}

// ---------------------------------------------------------------------------
// Shared GEMM geometry: CTA 128(m) x 128(n), 256 thr, 8 warps (4m x 2n),
// warp tile 32 x 64, K-chunk 32, 3-stage cp.async multistage, 2 CTAs/SM.
// Stage: Ah|Al|Wh|Wl, each 128x32 bf16 = 8 KB -> 32 KB/stage, 96 KB total.
// ---------------------------------------------------------------------------
#define OFF_AL  8192
#define OFF_WH  16384
#define OFF_WL  24576
#define STAGE_B 32768
#define SMEM_GEMM (1024 + 3 * STAGE_B)

// 3-term compute of one K32 chunk for warp tile 32x64, TERM-MAJOR order:
// all fragments loaded first, then 16 independent MMAs per term so each
// accumulator's RAW reuse distance is 16 (hides HMMA latency).
__device__ __forceinline__ void chunk_compute(uint32_t sb, int warp_m, int warp_n,
                                              int lane, float acc[2][8][4])
{
    const uint32_t sAh = sb, sAl = sb + OFF_AL;
    const uint32_t sWh = sb + OFF_WH, sWl = sb + OFF_WL;
    #pragma unroll
    for (int ks = 0; ks < 2; ++ks) {
        const int akb = ks * 32 + ((lane & 16) ? 16 : 0);
        uint32_t ah[2][4], al[2][4];
        #pragma unroll
        for (int mt = 0; mt < 2; ++mt) {
            const int row = warp_m + mt * 16 + (lane & 15);
            const uint32_t off = SW64((uint32_t)(row * 64 + akb));
            ldsm4(ah[mt], sAh + off);
            ldsm4(al[mt], sAl + off);
        }
        const int bkb = ks * 32 + ((lane & 8) ? 16 : 0);
        uint32_t wh[4][4];
        #pragma unroll
        for (int nt2 = 0; nt2 < 4; ++nt2) {
            const int brow = warp_n + nt2 * 16 + (lane & 7) + ((lane & 16) ? 8 : 0);
            ldsm4(wh[nt2], sWh + SW64((uint32_t)(brow * 64 + bkb)));
        }

        // Term 1: ah * wh  (16 independent MMAs)
        #pragma unroll
        for (int nt2 = 0; nt2 < 4; ++nt2)
            #pragma unroll
            for (int mt = 0; mt < 2; ++mt) {
                mma16816(acc[mt][nt2 * 2 + 0], ah[mt], wh[nt2][0], wh[nt2][1]);
                mma16816(acc[mt][nt2 * 2 + 1], ah[mt], wh[nt2][2], wh[nt2][3]);
            }

        // Issue wl loads; latency hides under term 2.
        uint32_t wl[4][4];
        #pragma unroll
        for (int nt2 = 0; nt2 < 4; ++nt2) {
            const int brow = warp_n + nt2 * 16 + (lane & 7) + ((lane & 16) ? 8 : 0);
            ldsm4(wl[nt2], sWl + SW64((uint32_t)(brow * 64 + bkb)));
        }

        // Term 2: al * wh
        #pragma unroll
        for (int nt2 = 0; nt2 < 4; ++nt2)
            #pragma unroll
            for (int mt = 0; mt < 2; ++mt) {
                mma16816(acc[mt][nt2 * 2 + 0], al[mt], wh[nt2][0], wh[nt2][1]);
                mma16816(acc[mt][nt2 * 2 + 1], al[mt], wh[nt2][2], wh[nt2][3]);
            }

        // Term 3: ah * wl
        #pragma unroll
        for (int nt2 = 0; nt2 < 4; ++nt2)
            #pragma unroll
            for (int mt = 0; mt < 2; ++mt) {
                mma16816(acc[mt][nt2 * 2 + 0], ah[mt], wl[nt2][0], wl[nt2][1]);
                mma16816(acc[mt][nt2 * 2 + 1], ah[mt], wl[nt2][2], wl[nt2][3]);
            }
    }
}

__device__ __forceinline__ void acc_zero(float acc[2][8][4]) {
    #pragma unroll
    for (int a = 0; a < 2; ++a)
        #pragma unroll
        for (int b = 0; b < 8; ++b)
            #pragma unroll
            for (int c = 0; c < 4; ++c) acc[a][b][c] = 0.0f;
}

// ---------------------------------------------------------------------------
// GEMM-1: 16 K32 chunks (0-7: x[:256]@w1, 8-15: x[256:]@w2). Grid (512, 4).
// ---------------------------------------------------------------------------
__global__ __launch_bounds__(256, 2)
void hmma_gemm1_kernel()
{
    extern __shared__ __align__(16) char smraw[];
    char* smem = smraw + ((1024 - (smem_u32(smraw) & 1023)) & 1023);
    const uint32_t sbase = smem_u32(smem);

    const int tid    = threadIdx.x;
    const int wid    = tid >> 5;
    const int lane   = tid & 31;
    const int warp_m = (wid & 3) * 32;
    const int warp_n = (wid >> 2) * 64;

    const int m0 = blockIdx.x * 128;
    const int n0 = blockIdx.y * 128;

    auto issue_chunk = [&](int c) {
        const uint32_t sb = sbase + (c % 3) * STAGE_B;
        const __nv_bfloat16* wh = (c >= 8) ? g_w2h : g_w1h;
        const __nv_bfloat16* wl = (c >= 8) ? g_w2l : g_w1l;
        const int kx = c * 32;
        const int kw = (c & 7) * 32;
        cp_tile32<128>(sb,          g_xh, D_,    m0, kx, tid);
        cp_tile32<128>(sb + OFF_AL, g_xl, D_,    m0, kx, tid);
        cp_tile32<128>(sb + OFF_WH, wh,   HALF_, n0, kw, tid);
        cp_tile32<128>(sb + OFF_WL, wl,   HALF_, n0, kw, tid);
        CP_COMMIT();
    };

    float acc[2][8][4];
    acc_zero(acc);

    issue_chunk(0);
    issue_chunk(1);

    #pragma unroll 1
    for (int c = 0; c < 16; ++c) {
        if (c < 15) { CP_WAIT1(); } else { CP_WAIT0(); }
        __syncthreads();
        if (c + 2 < 16) issue_chunk(c + 2);

        chunk_compute(sbase + (c % 3) * STAGE_B, warp_m, warp_n, lane, acc);

        if (c == 7 || c == 15) {
            float* dst = (c == 7) ? g_d1 : g_d2;
            #pragma unroll
            for (int mt = 0; mt < 2; ++mt) {
                #pragma unroll
                for (int half = 0; half < 2; ++half) {
                    const int m = m0 + warp_m + mt * 16 + (lane >> 2) + half * 8;
                    const int b = m >> 10;
                    const int t = m & (T_ - 1);
                    float* rowp = dst + (size_t)t * BH_ + (size_t)b * H_ + n0 + warp_n;
                    #pragma unroll
                    for (int nt = 0; nt < 8; ++nt) {
                        const int n = nt * 8 + (lane & 3) * 2;
                        float2 v = half ? make_float2(acc[mt][nt][2], acc[mt][nt][3])
                                        : make_float2(acc[mt][nt][0], acc[mt][nt][1]);
                        *(float2*)(rowp + n) = v;
                    }
                }
            }
            acc_zero(acc);
        }
    }
}

// ---------------------------------------------------------------------------
// Scan: sequential EMA over T; emits mems as bf16 hi/lo split.
// ---------------------------------------------------------------------------
__global__ __launch_bounds__(256)
void scan_kernel(const float* __restrict__ b1, const float* __restrict__ tau1,
                 const float* __restrict__ b2, const float* __restrict__ tau2)
{
    const int idx = blockIdx.x * blockDim.x + threadIdx.x;   // 0..32767
    const int h   = idx & (H_ - 1);

    const float a1 = 1.0f / (1.0f + __expf(-tau1[h]));
    const float a2 = 1.0f / (1.0f + __expf(-tau2[h]));
    const float c1 = 1.0f - a1;
    const float c2 = 1.0f - a2;
    const float bb1 = b1[h];
    const float bb2 = b2[h];

    float d1 = 0.0f, d2 = 0.0f, mem = 0.0f;

    #pragma unroll 1
    for (int t = 0; t < T_; t += 8) {
        float i1[8], i2[8];
        #pragma unroll
        for (int u = 0; u < 8; ++u) {
            i1[u] = g_d1[(size_t)(t + u) * BH_ + idx];
            i2[u] = g_d2[(size_t)(t + u) * BH_ + idx];
        }
        #pragma unroll
        for (int u = 0; u < 8; ++u) {
            d1  = a1 * d1 + c1 * (i1[u] + bb1);
            d2  = a2 * d2 + c2 * (i2[u] + bb2);
            mem = 0.8f * mem + 0.2f * (d1 + d2);
            const size_t off = (size_t)(t + u) * BH_ + idx;
            __nv_bfloat16 mh = __float2bfloat16(mem);
            __nv_bfloat16 ml = __float2bfloat16(mem - __bfloat162float(mh));
            g_mh[off] = mh;
            g_ml[off] = ml;
        }
    }
}

// ---------------------------------------------------------------------------
// GEMM-2: out = sigmoid(mems @ wo^T + bo). 16 K32 chunks. Grid (512).
// ---------------------------------------------------------------------------
__global__ __launch_bounds__(256, 2)
void hmma_gemm2_kernel(const float* __restrict__ bo, float* __restrict__ out)
{
    extern __shared__ __align__(16) char smraw[];
    char* smem = smraw + ((1024 - (smem_u32(smraw) & 1023)) & 1023);
    const uint32_t sbase = smem_u32(smem);

    const int tid    = threadIdx.x;
    const int wid    = tid >> 5;
    const int lane   = tid & 31;
    const int warp_m = (wid & 3) * 32;
    const int warp_n = (wid >> 2) * 64;

    const int m0 = blockIdx.x * 128;

    auto issue_chunk = [&](int c) {
        const uint32_t sb = sbase + (c % 3) * STAGE_B;
        const int k1 = c * 32;
        cp_tile32<128>(sb,          g_mh,  H_, m0, k1, tid);
        cp_tile32<128>(sb + OFF_AL, g_ml,  H_, m0, k1, tid);
        cp_tile32<128>(sb + OFF_WH, g_woh, H_, 0,  k1, tid);
        cp_tile32<128>(sb + OFF_WL, g_wol, H_, 0,  k1, tid);
        CP_COMMIT();
    };

    float acc[2][8][4];
    acc_zero(acc);

    issue_chunk(0);
    issue_chunk(1);

    #pragma unroll 1
    for (int c = 0; c < 16; ++c) {
        if (c < 15) { CP_WAIT1(); } else { CP_WAIT0(); }
        __syncthreads();
        if (c + 2 < 16) issue_chunk(c + 2);

        chunk_compute(sbase + (c % 3) * STAGE_B, warp_m, warp_n, lane, acc);
    }

    // Epilogue: bias + sigmoid; out[b,t,o], row m = t*B + b
    #pragma unroll
    for (int mt = 0; mt < 2; ++mt) {
        #pragma unroll
        for (int half = 0; half < 2; ++half) {
            const int m = m0 + warp_m + mt * 16 + (lane >> 2) + half * 8;
            const int t = m >> 6;           // / B_
            const int b = m & (B_ - 1);
            float* rowp = out + (size_t)b * (T_ * O_) + (size_t)t * O_ + warp_n;
            #pragma unroll
            for (int nt = 0; nt < 8; ++nt) {
                const int n = nt * 8 + (lane & 3) * 2;
                float v0 = half ? acc[mt][nt][2] : acc[mt][nt][0];
                float v1 = half ? acc[mt][nt][3] : acc[mt][nt][1];
                v0 += bo[warp_n + n];
                v1 += bo[warp_n + n + 1];
                v0 = 1.0f / (1.0f + __expf(-v0));
                v1 = 1.0f / (1.0f + __expf(-v1));
                *(float2*)(rowp + n) = make_float2(v0, v1);
            }
        }
    }
}

// ---------------------------------------------------------------------------
extern "C" void kernel_launch(void* const* d_in, const int* in_sizes, int n_in,
                              void* d_out, int out_size)
{
    const float* x    = (const float*)d_in[0];
    const float* w1   = (const float*)d_in[1];
    const float* b1   = (const float*)d_in[2];
    const float* tau1 = (const float*)d_in[3];
    const float* w2   = (const float*)d_in[4];
    const float* b2   = (const float*)d_in[5];
    const float* tau2 = (const float*)d_in[6];
    const float* wo   = (const float*)d_in[7];
    const float* bo   = (const float*)d_in[8];
    float* out = (float*)d_out;

    cudaFuncSetAttribute(hmma_gemm1_kernel,
                         cudaFuncAttributeMaxDynamicSharedMemorySize, SMEM_GEMM);
    cudaFuncSetAttribute(hmma_gemm2_kernel,
                         cudaFuncAttributeMaxDynamicSharedMemorySize, SMEM_GEMM);

    split_all_kernel<<<2048, 256>>>(x, w1, w2, wo);

    dim3 g1(M_ / 128, H_ / 128);          // 512 x 4
    hmma_gemm1_kernel<<<g1, 256, SMEM_GEMM>>>();

    scan_kernel<<<BH_ / 256, 256>>>(b1, tau1, b2, tau2);

    hmma_gemm2_kernel<<<M_ / 128, 256, SMEM_GEMM>>>(bo, out);
}

// round 11
// speedup vs baseline: 1.1615x; 1.1045x over previous
#include <cuda_runtime.h>
#include <cuda_fp16.h>
#include <cstdint>

// Problem constants
#define B_    64
#define T_    1024
#define D_    512
#define H_    512
#define O_    128
#define HALF_ 256
#define M_    (B_ * T_)          // 65536
#define BH_   (B_ * H_)          // 32768

// ---------------------------------------------------------------------------
// Device-global scratch
// ---------------------------------------------------------------------------
__device__ float   g_d1[T_ * B_ * H_];     // [T,B,H] fp32
__device__ float   g_d2[T_ * B_ * H_];     // [T,B,H] fp32
__device__ __half  g_xh[M_ * D_];          // x fp16 hi
__device__ __half  g_xl[M_ * D_];          // x fp16 lo
__device__ __half  g_w1[H_ * HALF_];       // w1 fp16
__device__ __half  g_w2[H_ * HALF_];       // w2 fp16
__device__ __half  g_wo[O_ * H_];          // wo fp16
__device__ __half  g_mh[T_ * B_ * H_];     // mems fp16 hi, row m = t*B+b
__device__ __half  g_ml[T_ * B_ * H_];     // mems fp16 lo

// ---------------------------------------------------------------------------
// Helpers
// ---------------------------------------------------------------------------
__device__ __forceinline__ uint32_t smem_u32(const void* p) {
    uint32_t a;
    asm("{ .reg .u64 t; cvta.to.shared.u64 t, %1; cvt.u32.u64 %0, t; }"
        : "=r"(a) : "l"(p));
    return a;
}
__device__ __forceinline__ void ldsm4(uint32_t r[4], uint32_t addr) {
    asm volatile("ldmatrix.sync.aligned.m8n8.x4.shared.b16 {%0,%1,%2,%3}, [%4];"
        : "=r"(r[0]), "=r"(r[1]), "=r"(r[2]), "=r"(r[3]) : "r"(addr));
}
__device__ __forceinline__ void mma16816(float c[4], const uint32_t a[4],
                                         const uint32_t b0, const uint32_t b1) {
    asm volatile(
        "mma.sync.aligned.m16n8k16.row.col.f32.f16.f16.f32 "
        "{%0,%1,%2,%3}, {%4,%5,%6,%7}, {%8,%9}, {%0,%1,%2,%3};"
        : "+f"(c[0]), "+f"(c[1]), "+f"(c[2]), "+f"(c[3])
        : "r"(a[0]), "r"(a[1]), "r"(a[2]), "r"(a[3]), "r"(b0), "r"(b1));
}
__device__ __forceinline__ void cp16(uint32_t dst, const void* src) {
    asm volatile("cp.async.cg.shared.global [%0], [%1], 16;"
        :: "r"(dst), "l"(src) : "memory");
}
#define CP_COMMIT() asm volatile("cp.async.commit_group;" ::: "memory")
#define CP_WAIT0()  asm volatile("cp.async.wait_group 0;" ::: "memory")
#define CP_WAIT1()  asm volatile("cp.async.wait_group 1;" ::: "memory")

// 64-byte rows (32 fp16), SW64 swizzle
#define SW64(o)   ((o) ^ (((o) >> 3) & 0x30))

// cp.async an R x 32 fp16 tile (K-major global) into SW64 smem. 256 threads.
template <int R>
__device__ __forceinline__ void cp_tile32(uint32_t sbase,
                                          const __half* __restrict__ g,
                                          int ld, int row0, int k0, int tid)
{
    #pragma unroll
    for (int i = 0; i < (R * 4) / 256; ++i) {
        const int slot = tid + i * 256;
        const int r = slot >> 2;
        const int v = slot & 3;
        cp16(sbase + SW64((uint32_t)(r * 64 + v * 16)),
             g + (size_t)(row0 + r) * ld + k0 + v * 8);
    }
}

// ---------------------------------------------------------------------------
// Fused split, one launch:
//   x -> fp16 hi/lo planes; w1, w2, wo -> single fp16 planes.
// ---------------------------------------------------------------------------
#define NXV  ((M_ * D_) / 4)
#define NWV  ((H_ * HALF_) / 4)
#define NOV  ((O_ * H_) / 4)

__device__ __forceinline__ void split_vec_hl(const float* src,
                                             __half* hi, __half* lo, int i)
{
    float4 v = ((const float4*)src)[i];
    float f[4] = {v.x, v.y, v.z, v.w};
    uint32_t ph[2], pl[2];
    #pragma unroll
    for (int j = 0; j < 2; ++j) {
        __half h0 = __float2half_rn(f[2*j]);
        __half h1 = __float2half_rn(f[2*j+1]);
        __half l0 = __float2half_rn(f[2*j]   - __half2float(h0));
        __half l1 = __float2half_rn(f[2*j+1] - __half2float(h1));
        ph[j] = (uint32_t)__half_as_ushort(h0) | ((uint32_t)__half_as_ushort(h1) << 16);
        pl[j] = (uint32_t)__half_as_ushort(l0) | ((uint32_t)__half_as_ushort(l1) << 16);
    }
    ((uint2*)hi)[i] = make_uint2(ph[0], ph[1]);
    ((uint2*)lo)[i] = make_uint2(pl[0], pl[1]);
}

__device__ __forceinline__ void cvt_vec(const float* src, __half* dst, int i)
{
    float4 v = ((const float4*)src)[i];
    float f[4] = {v.x, v.y, v.z, v.w};
    uint32_t p[2];
    #pragma unroll
    for (int j = 0; j < 2; ++j) {
        __half h0 = __float2half_rn(f[2*j]);
        __half h1 = __float2half_rn(f[2*j+1]);
        p[j] = (uint32_t)__half_as_ushort(h0) | ((uint32_t)__half_as_ushort(h1) << 16);
    }
    ((uint2*)dst)[i] = make_uint2(p[0], p[1]);
}

__global__ void split_all_kernel(const float* __restrict__ x,
                                 const float* __restrict__ w1,
                                 const float* __restrict__ w2,
                                 const float* __restrict__ wo)
{
    const int total = NXV + 2 * NWV + NOV;
    for (int i = blockIdx.x * blockDim.x + threadIdx.x; i < total;
         i += gridDim.x * blockDim.x) {
        if (i < NXV)                 split_vec_hl(x, g_xh, g_xl, i);
        else if (i < NXV + NWV)      cvt_vec(w1, g_w1, i - NXV);
        else if (i < NXV + 2 * NWV)  cvt_vec(w2, g_w2, i - NXV - NWV);
        else                         cvt_vec(wo, g_wo, i - NXV - 2 * NWV);
    }
}

// ---------------------------------------------------------------------------
// Shared GEMM geometry: CTA 128(m) x 128(n), 256 thr, 8 warps (4m x 2n),
// warp tile 32 x 64, K-chunk 32, 3-stage cp.async multistage, 2 CTAs/SM.
// Stage: Ah|Al|W, each 128x32 fp16 = 8 KB -> 24 KB/stage, 72 KB total.
// ---------------------------------------------------------------------------
#define OFF_AL  8192
#define OFF_W   16384
#define STAGE_B 24576
#define SMEM_GEMM (1024 + 3 * STAGE_B)

// 2-term fp16 compute of one K32 chunk for warp tile 32x64, term-major.
__device__ __forceinline__ void chunk_compute(uint32_t sb, int warp_m, int warp_n,
                                              int lane, float acc[2][8][4])
{
    const uint32_t sAh = sb, sAl = sb + OFF_AL, sW = sb + OFF_W;
    #pragma unroll
    for (int ks = 0; ks < 2; ++ks) {
        const int akb = ks * 32 + ((lane & 16) ? 16 : 0);
        uint32_t ah[2][4], al[2][4];
        #pragma unroll
        for (int mt = 0; mt < 2; ++mt) {
            const int row = warp_m + mt * 16 + (lane & 15);
            const uint32_t off = SW64((uint32_t)(row * 64 + akb));
            ldsm4(ah[mt], sAh + off);
            ldsm4(al[mt], sAl + off);
        }
        const int bkb = ks * 32 + ((lane & 8) ? 16 : 0);
        uint32_t w[4][4];
        #pragma unroll
        for (int nt2 = 0; nt2 < 4; ++nt2) {
            const int brow = warp_n + nt2 * 16 + (lane & 7) + ((lane & 16) ? 8 : 0);
            ldsm4(w[nt2], sW + SW64((uint32_t)(brow * 64 + bkb)));
        }

        // Term 1: ah * w   (16 independent MMAs)
        #pragma unroll
        for (int nt2 = 0; nt2 < 4; ++nt2)
            #pragma unroll
            for (int mt = 0; mt < 2; ++mt) {
                mma16816(acc[mt][nt2 * 2 + 0], ah[mt], w[nt2][0], w[nt2][1]);
                mma16816(acc[mt][nt2 * 2 + 1], ah[mt], w[nt2][2], w[nt2][3]);
            }
        // Term 2: al * w
        #pragma unroll
        for (int nt2 = 0; nt2 < 4; ++nt2)
            #pragma unroll
            for (int mt = 0; mt < 2; ++mt) {
                mma16816(acc[mt][nt2 * 2 + 0], al[mt], w[nt2][0], w[nt2][1]);
                mma16816(acc[mt][nt2 * 2 + 1], al[mt], w[nt2][2], w[nt2][3]);
            }
    }
}

__device__ __forceinline__ void acc_zero(float acc[2][8][4]) {
    #pragma unroll
    for (int a = 0; a < 2; ++a)
        #pragma unroll
        for (int b = 0; b < 8; ++b)
            #pragma unroll
            for (int c = 0; c < 4; ++c) acc[a][b][c] = 0.0f;
}

// ---------------------------------------------------------------------------
// GEMM-1: 16 K32 chunks (0-7: x[:256]@w1, 8-15: x[256:]@w2). Grid (512, 4).
// ---------------------------------------------------------------------------
__global__ __launch_bounds__(256, 2)
void hmma_gemm1_kernel()
{
    extern __shared__ __align__(16) char smraw[];
    char* smem = smraw + ((1024 - (smem_u32(smraw) & 1023)) & 1023);
    const uint32_t sbase = smem_u32(smem);

    const int tid    = threadIdx.x;
    const int wid    = tid >> 5;
    const int lane   = tid & 31;
    const int warp_m = (wid & 3) * 32;
    const int warp_n = (wid >> 2) * 64;

    const int m0 = blockIdx.x * 128;
    const int n0 = blockIdx.y * 128;

    auto issue_chunk = [&](int c) {
        const uint32_t sb = sbase + (c % 3) * STAGE_B;
        const __half* w = (c >= 8) ? g_w2 : g_w1;
        const int kx = c * 32;
        const int kw = (c & 7) * 32;
        cp_tile32<128>(sb,          g_xh, D_,    m0, kx, tid);
        cp_tile32<128>(sb + OFF_AL, g_xl, D_,    m0, kx, tid);
        cp_tile32<128>(sb + OFF_W,  w,    HALF_, n0, kw, tid);
        CP_COMMIT();
    };

    float acc[2][8][4];
    acc_zero(acc);

    issue_chunk(0);
    issue_chunk(1);

    #pragma unroll 1
    for (int c = 0; c < 16; ++c) {
        if (c < 15) { CP_WAIT1(); } else { CP_WAIT0(); }
        __syncthreads();
        if (c + 2 < 16) issue_chunk(c + 2);

        chunk_compute(sbase + (c % 3) * STAGE_B, warp_m, warp_n, lane, acc);

        if (c == 7 || c == 15) {
            float* dst = (c == 7) ? g_d1 : g_d2;
            #pragma unroll
            for (int mt = 0; mt < 2; ++mt) {
                #pragma unroll
                for (int half = 0; half < 2; ++half) {
                    const int m = m0 + warp_m + mt * 16 + (lane >> 2) + half * 8;
                    const int b = m >> 10;
                    const int t = m & (T_ - 1);
                    float* rowp = dst + (size_t)t * BH_ + (size_t)b * H_ + n0 + warp_n;
                    #pragma unroll
                    for (int nt = 0; nt < 8; ++nt) {
                        const int n = nt * 8 + (lane & 3) * 2;
                        float2 v = half ? make_float2(acc[mt][nt][2], acc[mt][nt][3])
                                        : make_float2(acc[mt][nt][0], acc[mt][nt][1]);
                        *(float2*)(rowp + n) = v;
                    }
                }
            }
            acc_zero(acc);
        }
    }
}

// ---------------------------------------------------------------------------
// Scan: sequential EMA over T; emits mems as fp16 hi/lo split.
// ---------------------------------------------------------------------------
__global__ __launch_bounds__(256)
void scan_kernel(const float* __restrict__ b1, const float* __restrict__ tau1,
                 const float* __restrict__ b2, const float* __restrict__ tau2)
{
    const int idx = blockIdx.x * blockDim.x + threadIdx.x;   // 0..32767
    const int h   = idx & (H_ - 1);

    const float a1 = 1.0f / (1.0f + __expf(-tau1[h]));
    const float a2 = 1.0f / (1.0f + __expf(-tau2[h]));
    const float c1 = 1.0f - a1;
    const float c2 = 1.0f - a2;
    const float bb1 = b1[h];
    const float bb2 = b2[h];

    float d1 = 0.0f, d2 = 0.0f, mem = 0.0f;

    #pragma unroll 1
    for (int t = 0; t < T_; t += 8) {
        float i1[8], i2[8];
        #pragma unroll
        for (int u = 0; u < 8; ++u) {
            i1[u] = g_d1[(size_t)(t + u) * BH_ + idx];
            i2[u] = g_d2[(size_t)(t + u) * BH_ + idx];
        }
        #pragma unroll
        for (int u = 0; u < 8; ++u) {
            d1  = a1 * d1 + c1 * (i1[u] + bb1);
            d2  = a2 * d2 + c2 * (i2[u] + bb2);
            mem = 0.8f * mem + 0.2f * (d1 + d2);
            const size_t off = (size_t)(t + u) * BH_ + idx;
            __half mh = __float2half_rn(mem);
            __half ml = __float2half_rn(mem - __half2float(mh));
            g_mh[off] = mh;
            g_ml[off] = ml;
        }
    }
}

// ---------------------------------------------------------------------------
// GEMM-2: out = sigmoid(mems @ wo^T + bo). 16 K32 chunks. Grid (512).
// ---------------------------------------------------------------------------
__global__ __launch_bounds__(256, 2)
void hmma_gemm2_kernel(const float* __restrict__ bo, float* __restrict__ out)
{
    extern __shared__ __align__(16) char smraw[];
    char* smem = smraw + ((1024 - (smem_u32(smraw) & 1023)) & 1023);
    const uint32_t sbase = smem_u32(smem);

    const int tid    = threadIdx.x;
    const int wid    = tid >> 5;
    const int lane   = tid & 31;
    const int warp_m = (wid & 3) * 32;
    const int warp_n = (wid >> 2) * 64;

    const int m0 = blockIdx.x * 128;

    auto issue_chunk = [&](int c) {
        const uint32_t sb = sbase + (c % 3) * STAGE_B;
        const int k1 = c * 32;
        cp_tile32<128>(sb,          g_mh, H_, m0, k1, tid);
        cp_tile32<128>(sb + OFF_AL, g_ml, H_, m0, k1, tid);
        cp_tile32<128>(sb + OFF_W,  g_wo, H_, 0,  k1, tid);
        CP_COMMIT();
    };

    float acc[2][8][4];
    acc_zero(acc);

    issue_chunk(0);
    issue_chunk(1);

    #pragma unroll 1
    for (int c = 0; c < 16; ++c) {
        if (c < 15) { CP_WAIT1(); } else { CP_WAIT0(); }
        __syncthreads();
        if (c + 2 < 16) issue_chunk(c + 2);

        chunk_compute(sbase + (c % 3) * STAGE_B, warp_m, warp_n, lane, acc);
    }

    // Epilogue: bias + sigmoid; out[b,t,o], row m = t*B + b
    #pragma unroll
    for (int mt = 0; mt < 2; ++mt) {
        #pragma unroll
        for (int half = 0; half < 2; ++half) {
            const int m = m0 + warp_m + mt * 16 + (lane >> 2) + half * 8;
            const int t = m >> 6;           // / B_
            const int b = m & (B_ - 1);
            float* rowp = out + (size_t)b * (T_ * O_) + (size_t)t * O_ + warp_n;
            #pragma unroll
            for (int nt = 0; nt < 8; ++nt) {
                const int n = nt * 8 + (lane & 3) * 2;
                float v0 = half ? acc[mt][nt][2] : acc[mt][nt][0];
                float v1 = half ? acc[mt][nt][3] : acc[mt][nt][1];
                v0 += bo[warp_n + n];
                v1 += bo[warp_n + n + 1];
                v0 = 1.0f / (1.0f + __expf(-v0));
                v1 = 1.0f / (1.0f + __expf(-v1));
                *(float2*)(rowp + n) = make_float2(v0, v1);
            }
        }
    }
}

// ---------------------------------------------------------------------------
extern "C" void kernel_launch(void* const* d_in, const int* in_sizes, int n_in,
                              void* d_out, int out_size)
{
    const float* x    = (const float*)d_in[0];
    const float* w1   = (const float*)d_in[1];
    const float* b1   = (const float*)d_in[2];
    const float* tau1 = (const float*)d_in[3];
    const float* w2   = (const float*)d_in[4];
    const float* b2   = (const float*)d_in[5];
    const float* tau2 = (const float*)d_in[6];
    const float* wo   = (const float*)d_in[7];
    const float* bo   = (const float*)d_in[8];
    float* out = (float*)d_out;

    cudaFuncSetAttribute(hmma_gemm1_kernel,
                         cudaFuncAttributeMaxDynamicSharedMemorySize, SMEM_GEMM);
    cudaFuncSetAttribute(hmma_gemm2_kernel,
                         cudaFuncAttributeMaxDynamicSharedMemorySize, SMEM_GEMM);

    split_all_kernel<<<2048, 256>>>(x, w1, w2, wo);

    dim3 g1(M_ / 128, H_ / 128);          // 512 x 4
    hmma_gemm1_kernel<<<g1, 256, SMEM_GEMM>>>();

    scan_kernel<<<BH_ / 256, 256>>>(b1, tau1, b2, tau2);

    hmma_gemm2_kernel<<<M_ / 128, 256, SMEM_GEMM>>>(bo, out);
}

// round 12
// speedup vs baseline: 1.4409x; 1.2406x over previous
#include <cuda_runtime.h>
#include <cuda_fp16.h>
#include <cstdint>

// Problem constants
#define B_    64
#define T_    1024
#define D_    512
#define H_    512
#define O_    128
#define HALF_ 256
#define M_    (B_ * T_)          // 65536
#define BH_   (B_ * H_)          // 32768

// ---------------------------------------------------------------------------
// Device-global scratch (all fp16 single-plane)
// ---------------------------------------------------------------------------
__device__ __half  g_d1[T_ * B_ * H_];     // [T,B,H] fp16
__device__ __half  g_d2[T_ * B_ * H_];     // [T,B,H] fp16
__device__ __half  g_x16[M_ * D_];         // x fp16
__device__ __half  g_w1[H_ * HALF_];       // w1 fp16
__device__ __half  g_w2[H_ * HALF_];       // w2 fp16
__device__ __half  g_wo[O_ * H_];          // wo fp16
__device__ __half  g_m16[T_ * B_ * H_];    // mems fp16, row m = t*B+b

// ---------------------------------------------------------------------------
// Helpers
// ---------------------------------------------------------------------------
__device__ __forceinline__ uint32_t smem_u32(const void* p) {
    uint32_t a;
    asm("{ .reg .u64 t; cvta.to.shared.u64 t, %1; cvt.u32.u64 %0, t; }"
        : "=r"(a) : "l"(p));
    return a;
}
__device__ __forceinline__ void ldsm4(uint32_t r[4], uint32_t addr) {
    asm volatile("ldmatrix.sync.aligned.m8n8.x4.shared.b16 {%0,%1,%2,%3}, [%4];"
        : "=r"(r[0]), "=r"(r[1]), "=r"(r[2]), "=r"(r[3]) : "r"(addr));
}
__device__ __forceinline__ void mma16816(float c[4], const uint32_t a[4],
                                         const uint32_t b0, const uint32_t b1) {
    asm volatile(
        "mma.sync.aligned.m16n8k16.row.col.f32.f16.f16.f32 "
        "{%0,%1,%2,%3}, {%4,%5,%6,%7}, {%8,%9}, {%0,%1,%2,%3};"
        : "+f"(c[0]), "+f"(c[1]), "+f"(c[2]), "+f"(c[3])
        : "r"(a[0]), "r"(a[1]), "r"(a[2]), "r"(a[3]), "r"(b0), "r"(b1));
}
__device__ __forceinline__ void cp16(uint32_t dst, const void* src) {
    asm volatile("cp.async.cg.shared.global [%0], [%1], 16;"
        :: "r"(dst), "l"(src) : "memory");
}
#define CP_COMMIT() asm volatile("cp.async.commit_group;" ::: "memory")
#define CP_WAIT0()  asm volatile("cp.async.wait_group 0;" ::: "memory")
#define CP_WAIT1()  asm volatile("cp.async.wait_group 1;" ::: "memory")

// 64-byte rows (32 fp16), SW64 swizzle
#define SW64(o)   ((o) ^ (((o) >> 3) & 0x30))

// cp.async an R x 32 fp16 tile (K-major global) into SW64 smem. 256 threads.
template <int R>
__device__ __forceinline__ void cp_tile32(uint32_t sbase,
                                          const __half* __restrict__ g,
                                          int ld, int row0, int k0, int tid)
{
    #pragma unroll
    for (int i = 0; i < (R * 4) / 256; ++i) {
        const int slot = tid + i * 256;
        const int r = slot >> 2;
        const int v = slot & 3;
        cp16(sbase + SW64((uint32_t)(r * 64 + v * 16)),
             g + (size_t)(row0 + r) * ld + k0 + v * 8);
    }
}

// ---------------------------------------------------------------------------
// Fused convert: x, w1, w2, wo -> single fp16 planes, one launch.
// ---------------------------------------------------------------------------
#define NXV  ((M_ * D_) / 4)
#define NWV  ((H_ * HALF_) / 4)
#define NOV  ((O_ * H_) / 4)

__device__ __forceinline__ void cvt_vec(const float* src, __half* dst, int i)
{
    float4 v = ((const float4*)src)[i];
    float f[4] = {v.x, v.y, v.z, v.w};
    uint32_t p[2];
    #pragma unroll
    for (int j = 0; j < 2; ++j) {
        __half h0 = __float2half_rn(f[2*j]);
        __half h1 = __float2half_rn(f[2*j+1]);
        p[j] = (uint32_t)__half_as_ushort(h0) | ((uint32_t)__half_as_ushort(h1) << 16);
    }
    ((uint2*)dst)[i] = make_uint2(p[0], p[1]);
}

__global__ void split_all_kernel(const float* __restrict__ x,
                                 const float* __restrict__ w1,
                                 const float* __restrict__ w2,
                                 const float* __restrict__ wo)
{
    const int total = NXV + 2 * NWV + NOV;
    for (int i = blockIdx.x * blockDim.x + threadIdx.x; i < total;
         i += gridDim.x * blockDim.x) {
        if (i < NXV)                 cvt_vec(x,  g_x16, i);
        else if (i < NXV + NWV)      cvt_vec(w1, g_w1,  i - NXV);
        else if (i < NXV + 2 * NWV)  cvt_vec(w2, g_w2,  i - NXV - NWV);
        else                         cvt_vec(wo, g_wo,  i - NXV - 2 * NWV);
    }
}

// ---------------------------------------------------------------------------
// Shared GEMM geometry: CTA 128(m) x 128(n), 256 thr, 8 warps (4m x 2n),
// warp tile 32 x 64, K-chunk 32, 3-stage cp.async multistage, 2 CTAs/SM.
// Stage: A|W, each 128x32 fp16 = 8 KB -> 16 KB/stage, 48 KB total.
// ---------------------------------------------------------------------------
#define OFF_W   8192
#define STAGE_B 16384
#define SMEM_GEMM (1024 + 3 * STAGE_B)

// 1-term fp16 compute of one K32 chunk for warp tile 32x64, term-major.
__device__ __forceinline__ void chunk_compute(uint32_t sb, int warp_m, int warp_n,
                                              int lane, float acc[2][8][4])
{
    const uint32_t sA = sb, sW = sb + OFF_W;
    #pragma unroll
    for (int ks = 0; ks < 2; ++ks) {
        const int akb = ks * 32 + ((lane & 16) ? 16 : 0);
        uint32_t a[2][4];
        #pragma unroll
        for (int mt = 0; mt < 2; ++mt) {
            const int row = warp_m + mt * 16 + (lane & 15);
            ldsm4(a[mt], sA + SW64((uint32_t)(row * 64 + akb)));
        }
        const int bkb = ks * 32 + ((lane & 8) ? 16 : 0);
        uint32_t w[4][4];
        #pragma unroll
        for (int nt2 = 0; nt2 < 4; ++nt2) {
            const int brow = warp_n + nt2 * 16 + (lane & 7) + ((lane & 16) ? 8 : 0);
            ldsm4(w[nt2], sW + SW64((uint32_t)(brow * 64 + bkb)));
        }
        #pragma unroll
        for (int nt2 = 0; nt2 < 4; ++nt2)
            #pragma unroll
            for (int mt = 0; mt < 2; ++mt) {
                mma16816(acc[mt][nt2 * 2 + 0], a[mt], w[nt2][0], w[nt2][1]);
                mma16816(acc[mt][nt2 * 2 + 1], a[mt], w[nt2][2], w[nt2][3]);
            }
    }
}

__device__ __forceinline__ void acc_zero(float acc[2][8][4]) {
    #pragma unroll
    for (int a = 0; a < 2; ++a)
        #pragma unroll
        for (int b = 0; b < 8; ++b)
            #pragma unroll
            for (int c = 0; c < 4; ++c) acc[a][b][c] = 0.0f;
}

// ---------------------------------------------------------------------------
// GEMM-1: 16 K32 chunks (0-7: x[:256]@w1 -> d1, 8-15: x[256:]@w2 -> d2).
// Grid (512, 4). Outputs fp16.
// ---------------------------------------------------------------------------
__global__ __launch_bounds__(256, 2)
void hmma_gemm1_kernel()
{
    extern __shared__ __align__(16) char smraw[];
    char* smem = smraw + ((1024 - (smem_u32(smraw) & 1023)) & 1023);
    const uint32_t sbase = smem_u32(smem);

    const int tid    = threadIdx.x;
    const int wid    = tid >> 5;
    const int lane   = tid & 31;
    const int warp_m = (wid & 3) * 32;
    const int warp_n = (wid >> 2) * 64;

    const int m0 = blockIdx.x * 128;
    const int n0 = blockIdx.y * 128;

    auto issue_chunk = [&](int c) {
        const uint32_t sb = sbase + (c % 3) * STAGE_B;
        const __half* w = (c >= 8) ? g_w2 : g_w1;
        const int kx = c * 32;
        const int kw = (c & 7) * 32;
        cp_tile32<128>(sb,         g_x16, D_,    m0, kx, tid);
        cp_tile32<128>(sb + OFF_W, w,     HALF_, n0, kw, tid);
        CP_COMMIT();
    };

    float acc[2][8][4];
    acc_zero(acc);

    issue_chunk(0);
    issue_chunk(1);

    #pragma unroll 1
    for (int c = 0; c < 16; ++c) {
        if (c < 15) { CP_WAIT1(); } else { CP_WAIT0(); }
        __syncthreads();
        if (c + 2 < 16) issue_chunk(c + 2);

        chunk_compute(sbase + (c % 3) * STAGE_B, warp_m, warp_n, lane, acc);

        if (c == 7 || c == 15) {
            __half* dst = (c == 7) ? g_d1 : g_d2;
            #pragma unroll
            for (int mt = 0; mt < 2; ++mt) {
                #pragma unroll
                for (int half = 0; half < 2; ++half) {
                    const int m = m0 + warp_m + mt * 16 + (lane >> 2) + half * 8;
                    const int b = m >> 10;
                    const int t = m & (T_ - 1);
                    __half* rowp = dst + (size_t)t * BH_ + (size_t)b * H_ + n0 + warp_n;
                    #pragma unroll
                    for (int nt = 0; nt < 8; ++nt) {
                        const int n = nt * 8 + (lane & 3) * 2;
                        float v0 = half ? acc[mt][nt][2] : acc[mt][nt][0];
                        float v1 = half ? acc[mt][nt][3] : acc[mt][nt][1];
                        *(__half2*)(rowp + n) = __floats2half2_rn(v0, v1);
                    }
                }
            }
            acc_zero(acc);
        }
    }
}

// ---------------------------------------------------------------------------
// Scan: sequential EMA over T. One thread per (b, h-pair), half2 I/O.
// ---------------------------------------------------------------------------
__global__ __launch_bounds__(128)
void scan_kernel(const float* __restrict__ b1, const float* __restrict__ tau1,
                 const float* __restrict__ b2, const float* __restrict__ tau2)
{
    const int idx = blockIdx.x * blockDim.x + threadIdx.x;   // 0..16383
    const int h0  = (idx & 255) * 2;

    const float a1x = 1.0f / (1.0f + __expf(-tau1[h0]));
    const float a1y = 1.0f / (1.0f + __expf(-tau1[h0 + 1]));
    const float a2x = 1.0f / (1.0f + __expf(-tau2[h0]));
    const float a2y = 1.0f / (1.0f + __expf(-tau2[h0 + 1]));
    const float c1x = 1.0f - a1x, c1y = 1.0f - a1y;
    const float c2x = 1.0f - a2x, c2y = 1.0f - a2y;
    const float b1x = b1[h0], b1y = b1[h0 + 1];
    const float b2x = b2[h0], b2y = b2[h0 + 1];

    const __half2* d1p = (const __half2*)g_d1;
    const __half2* d2p = (const __half2*)g_d2;
    __half2* mp = (__half2*)g_m16;
    const int stride = BH_ / 2;   // 16384

    float d1vx = 0.f, d1vy = 0.f, d2vx = 0.f, d2vy = 0.f, memx = 0.f, memy = 0.f;

    #pragma unroll 1
    for (int t = 0; t < T_; t += 8) {
        __half2 i1[8], i2[8];
        #pragma unroll
        for (int u = 0; u < 8; ++u) {
            i1[u] = d1p[(size_t)(t + u) * stride + idx];
            i2[u] = d2p[(size_t)(t + u) * stride + idx];
        }
        #pragma unroll
        for (int u = 0; u < 8; ++u) {
            float2 f1 = __half22float2(i1[u]);
            float2 f2 = __half22float2(i2[u]);
            d1vx = a1x * d1vx + c1x * (f1.x + b1x);
            d1vy = a1y * d1vy + c1y * (f1.y + b1y);
            d2vx = a2x * d2vx + c2x * (f2.x + b2x);
            d2vy = a2y * d2vy + c2y * (f2.y + b2y);
            memx = 0.8f * memx + 0.2f * (d1vx + d2vx);
            memy = 0.8f * memy + 0.2f * (d1vy + d2vy);
            mp[(size_t)(t + u) * stride + idx] = __floats2half2_rn(memx, memy);
        }
    }
}

// ---------------------------------------------------------------------------
// GEMM-2: out = sigmoid(mems @ wo^T + bo). 16 K32 chunks. Grid (512).
// ---------------------------------------------------------------------------
__global__ __launch_bounds__(256, 2)
void hmma_gemm2_kernel(const float* __restrict__ bo, float* __restrict__ out)
{
    extern __shared__ __align__(16) char smraw[];
    char* smem = smraw + ((1024 - (smem_u32(smraw) & 1023)) & 1023);
    const uint32_t sbase = smem_u32(smem);

    const int tid    = threadIdx.x;
    const int wid    = tid >> 5;
    const int lane   = tid & 31;
    const int warp_m = (wid & 3) * 32;
    const int warp_n = (wid >> 2) * 64;

    const int m0 = blockIdx.x * 128;

    auto issue_chunk = [&](int c) {
        const uint32_t sb = sbase + (c % 3) * STAGE_B;
        const int k1 = c * 32;
        cp_tile32<128>(sb,         g_m16, H_, m0, k1, tid);
        cp_tile32<128>(sb + OFF_W, g_wo,  H_, 0,  k1, tid);
        CP_COMMIT();
    };

    float acc[2][8][4];
    acc_zero(acc);

    issue_chunk(0);
    issue_chunk(1);

    #pragma unroll 1
    for (int c = 0; c < 16; ++c) {
        if (c < 15) { CP_WAIT1(); } else { CP_WAIT0(); }
        __syncthreads();
        if (c + 2 < 16) issue_chunk(c + 2);

        chunk_compute(sbase + (c % 3) * STAGE_B, warp_m, warp_n, lane, acc);
    }

    // Epilogue: bias + sigmoid; out[b,t,o], row m = t*B + b
    #pragma unroll
    for (int mt = 0; mt < 2; ++mt) {
        #pragma unroll
        for (int half = 0; half < 2; ++half) {
            const int m = m0 + warp_m + mt * 16 + (lane >> 2) + half * 8;
            const int t = m >> 6;           // / B_
            const int b = m & (B_ - 1);
            float* rowp = out + (size_t)b * (T_ * O_) + (size_t)t * O_ + warp_n;
            #pragma unroll
            for (int nt = 0; nt < 8; ++nt) {
                const int n = nt * 8 + (lane & 3) * 2;
                float v0 = half ? acc[mt][nt][2] : acc[mt][nt][0];
                float v1 = half ? acc[mt][nt][3] : acc[mt][nt][1];
                v0 += bo[warp_n + n];
                v1 += bo[warp_n + n + 1];
                v0 = 1.0f / (1.0f + __expf(-v0));
                v1 = 1.0f / (1.0f + __expf(-v1));
                *(float2*)(rowp + n) = make_float2(v0, v1);
            }
        }
    }
}

// ---------------------------------------------------------------------------
extern "C" void kernel_launch(void* const* d_in, const int* in_sizes, int n_in,
                              void* d_out, int out_size)
{
    const float* x    = (const float*)d_in[0];
    const float* w1   = (const float*)d_in[1];
    const float* b1   = (const float*)d_in[2];
    const float* tau1 = (const float*)d_in[3];
    const float* w2   = (const float*)d_in[4];
    const float* b2   = (const float*)d_in[5];
    const float* tau2 = (const float*)d_in[6];
    const float* wo   = (const float*)d_in[7];
    const float* bo   = (const float*)d_in[8];
    float* out = (float*)d_out;

    cudaFuncSetAttribute(hmma_gemm1_kernel,
                         cudaFuncAttributeMaxDynamicSharedMemorySize, SMEM_GEMM);
    cudaFuncSetAttribute(hmma_gemm2_kernel,
                         cudaFuncAttributeMaxDynamicSharedMemorySize, SMEM_GEMM);

    split_all_kernel<<<2048, 256>>>(x, w1, w2, wo);

    dim3 g1(M_ / 128, H_ / 128);          // 512 x 4
    hmma_gemm1_kernel<<<g1, 256, SMEM_GEMM>>>();

    scan_kernel<<<(BH_ / 2) / 128, 128>>>(b1, tau1, b2, tau2);

    hmma_gemm2_kernel<<<M_ / 128, 256, SMEM_GEMM>>>(bo, out);
}

// round 13
// speedup vs baseline: 1.5124x; 1.0496x over previous
#include <cuda_runtime.h>
#include <cuda_fp16.h>
#include <cstdint>

// Problem constants
#define B_    64
#define T_    1024
#define D_    512
#define H_    512
#define O_    128
#define HALF_ 256
#define M_    (B_ * T_)          // 65536
#define BH_   (B_ * H_)          // 32768

// ---------------------------------------------------------------------------
// Device-global scratch (all fp16 single-plane)
// ---------------------------------------------------------------------------
__device__ __half  g_d1[T_ * B_ * H_];     // [T,B,H] fp16
__device__ __half  g_d2[T_ * B_ * H_];     // [T,B,H] fp16
__device__ __half  g_x16[M_ * D_];         // x fp16
__device__ __half  g_w1[H_ * HALF_];       // w1 fp16
__device__ __half  g_w2[H_ * HALF_];       // w2 fp16
__device__ __half  g_wo[O_ * H_];          // wo fp16
__device__ __half  g_m16[T_ * B_ * H_];    // mems fp16, row m = t*B+b

// ---------------------------------------------------------------------------
// Helpers
// ---------------------------------------------------------------------------
__device__ __forceinline__ uint32_t smem_u32(const void* p) {
    uint32_t a;
    asm("{ .reg .u64 t; cvta.to.shared.u64 t, %1; cvt.u32.u64 %0, t; }"
        : "=r"(a) : "l"(p));
    return a;
}
__device__ __forceinline__ void ldsm4(uint32_t r[4], uint32_t addr) {
    asm volatile("ldmatrix.sync.aligned.m8n8.x4.shared.b16 {%0,%1,%2,%3}, [%4];"
        : "=r"(r[0]), "=r"(r[1]), "=r"(r[2]), "=r"(r[3]) : "r"(addr));
}
__device__ __forceinline__ void mma16816(float c[4], const uint32_t a[4],
                                         const uint32_t b0, const uint32_t b1) {
    asm volatile(
        "mma.sync.aligned.m16n8k16.row.col.f32.f16.f16.f32 "
        "{%0,%1,%2,%3}, {%4,%5,%6,%7}, {%8,%9}, {%0,%1,%2,%3};"
        : "+f"(c[0]), "+f"(c[1]), "+f"(c[2]), "+f"(c[3])
        : "r"(a[0]), "r"(a[1]), "r"(a[2]), "r"(a[3]), "r"(b0), "r"(b1));
}
__device__ __forceinline__ void cp16(uint32_t dst, const void* src) {
    asm volatile("cp.async.cg.shared.global [%0], [%1], 16;"
        :: "r"(dst), "l"(src) : "memory");
}
#define CP_COMMIT() asm volatile("cp.async.commit_group;" ::: "memory")
#define CP_WAIT0()  asm volatile("cp.async.wait_group 0;" ::: "memory")
#define CP_WAIT1()  asm volatile("cp.async.wait_group 1;" ::: "memory")

// 128-byte rows (64 fp16), SW128 swizzle
#define SW128(o)   ((o) ^ (((o) >> 3) & 0x70))

// cp.async an R x 64 fp16 tile (K-major global) into SW128 smem. 256 threads.
template <int R>
__device__ __forceinline__ void cp_tile64(uint32_t sbase,
                                          const __half* __restrict__ g,
                                          int ld, int row0, int k0, int tid)
{
    #pragma unroll
    for (int i = 0; i < (R * 8) / 256; ++i) {
        const int slot = tid + i * 256;
        const int r = slot >> 3;
        const int v = slot & 7;
        cp16(sbase + SW128((uint32_t)(r * 128 + v * 16)),
             g + (size_t)(row0 + r) * ld + k0 + v * 8);
    }
}

// ---------------------------------------------------------------------------
// Fused convert: x, w1, w2, wo -> single fp16 planes, one launch.
// ---------------------------------------------------------------------------
#define NXV  ((M_ * D_) / 4)
#define NWV  ((H_ * HALF_) / 4)
#define NOV  ((O_ * H_) / 4)

__device__ __forceinline__ void cvt_vec(const float* src, __half* dst, int i)
{
    float4 v = __ldcs(&((const float4*)src)[i]);
    float f[4] = {v.x, v.y, v.z, v.w};
    uint32_t p[2];
    #pragma unroll
    for (int j = 0; j < 2; ++j) {
        __half h0 = __float2half_rn(f[2*j]);
        __half h1 = __float2half_rn(f[2*j+1]);
        p[j] = (uint32_t)__half_as_ushort(h0) | ((uint32_t)__half_as_ushort(h1) << 16);
    }
    __stcs(&((uint2*)dst)[i], make_uint2(p[0], p[1]));
}

__global__ void split_all_kernel(const float* __restrict__ x,
                                 const float* __restrict__ w1,
                                 const float* __restrict__ w2,
                                 const float* __restrict__ wo)
{
    const int total = NXV + 2 * NWV + NOV;
    for (int i = blockIdx.x * blockDim.x + threadIdx.x; i < total;
         i += gridDim.x * blockDim.x) {
        if (i < NXV)                 cvt_vec(x,  g_x16, i);
        else if (i < NXV + NWV)      cvt_vec(w1, g_w1,  i - NXV);
        else if (i < NXV + 2 * NWV)  cvt_vec(w2, g_w2,  i - NXV - NWV);
        else                         cvt_vec(wo, g_wo,  i - NXV - 2 * NWV);
    }
}

// ---------------------------------------------------------------------------
// Shared GEMM geometry: CTA 128(m) x 128(n), 256 thr, 8 warps (4m x 2n),
// warp tile 32 x 64, K-chunk 64, 3-stage cp.async multistage, 2 CTAs/SM.
// Stage: A|W, each 128x64 fp16 = 16 KB -> 32 KB/stage, 96 KB total.
// ---------------------------------------------------------------------------
#define OFF_W   16384
#define STAGE_B 32768
#define SMEM_GEMM (1024 + 3 * STAGE_B)

// 1-term fp16 compute of one K64 chunk for warp tile 32x64.
__device__ __forceinline__ void chunk_compute(uint32_t sb, int warp_m, int warp_n,
                                              int lane, float acc[2][8][4])
{
    const uint32_t sA = sb, sW = sb + OFF_W;
    #pragma unroll
    for (int ks = 0; ks < 4; ++ks) {
        const int akb = ks * 32 + ((lane & 16) ? 16 : 0);
        uint32_t a[2][4];
        #pragma unroll
        for (int mt = 0; mt < 2; ++mt) {
            const int row = warp_m + mt * 16 + (lane & 15);
            ldsm4(a[mt], sA + SW128((uint32_t)(row * 128 + akb)));
        }
        const int bkb = ks * 32 + ((lane & 8) ? 16 : 0);
        uint32_t w[4][4];
        #pragma unroll
        for (int nt2 = 0; nt2 < 4; ++nt2) {
            const int brow = warp_n + nt2 * 16 + (lane & 7) + ((lane & 16) ? 8 : 0);
            ldsm4(w[nt2], sW + SW128((uint32_t)(brow * 128 + bkb)));
        }
        #pragma unroll
        for (int nt2 = 0; nt2 < 4; ++nt2)
            #pragma unroll
            for (int mt = 0; mt < 2; ++mt) {
                mma16816(acc[mt][nt2 * 2 + 0], a[mt], w[nt2][0], w[nt2][1]);
                mma16816(acc[mt][nt2 * 2 + 1], a[mt], w[nt2][2], w[nt2][3]);
            }
    }
}

__device__ __forceinline__ void acc_zero(float acc[2][8][4]) {
    #pragma unroll
    for (int a = 0; a < 2; ++a)
        #pragma unroll
        for (int b = 0; b < 8; ++b)
            #pragma unroll
            for (int c = 0; c < 4; ++c) acc[a][b][c] = 0.0f;
}

// ---------------------------------------------------------------------------
// GEMM-1: 8 K64 chunks (0-3: x[:256]@w1 -> d1, 4-7: x[256:]@w2 -> d2).
// Grid (512, 4). Outputs fp16.
// ---------------------------------------------------------------------------
__global__ __launch_bounds__(256, 2)
void hmma_gemm1_kernel()
{
    extern __shared__ __align__(16) char smraw[];
    char* smem = smraw + ((1024 - (smem_u32(smraw) & 1023)) & 1023);
    const uint32_t sbase = smem_u32(smem);

    const int tid    = threadIdx.x;
    const int wid    = tid >> 5;
    const int lane   = tid & 31;
    const int warp_m = (wid & 3) * 32;
    const int warp_n = (wid >> 2) * 64;

    const int m0 = blockIdx.x * 128;
    const int n0 = blockIdx.y * 128;

    auto issue_chunk = [&](int c) {
        const uint32_t sb = sbase + (c % 3) * STAGE_B;
        const __half* w = (c >= 4) ? g_w2 : g_w1;
        const int kx = c * 64;
        const int kw = (c & 3) * 64;
        cp_tile64<128>(sb,         g_x16, D_,    m0, kx, tid);
        cp_tile64<128>(sb + OFF_W, w,     HALF_, n0, kw, tid);
        CP_COMMIT();
    };

    float acc[2][8][4];
    acc_zero(acc);

    issue_chunk(0);
    issue_chunk(1);

    #pragma unroll 1
    for (int c = 0; c < 8; ++c) {
        if (c < 7) { CP_WAIT1(); } else { CP_WAIT0(); }
        __syncthreads();
        if (c + 2 < 8) issue_chunk(c + 2);

        chunk_compute(sbase + (c % 3) * STAGE_B, warp_m, warp_n, lane, acc);

        if (c == 3 || c == 7) {
            __half* dst = (c == 3) ? g_d1 : g_d2;
            #pragma unroll
            for (int mt = 0; mt < 2; ++mt) {
                #pragma unroll
                for (int half = 0; half < 2; ++half) {
                    const int m = m0 + warp_m + mt * 16 + (lane >> 2) + half * 8;
                    const int b = m >> 10;
                    const int t = m & (T_ - 1);
                    __half* rowp = dst + (size_t)t * BH_ + (size_t)b * H_ + n0 + warp_n;
                    #pragma unroll
                    for (int nt = 0; nt < 8; ++nt) {
                        const int n = nt * 8 + (lane & 3) * 2;
                        float v0 = half ? acc[mt][nt][2] : acc[mt][nt][0];
                        float v1 = half ? acc[mt][nt][3] : acc[mt][nt][1];
                        *(__half2*)(rowp + n) = __floats2half2_rn(v0, v1);
                    }
                }
            }
            acc_zero(acc);
        }
    }
}

// ---------------------------------------------------------------------------
// Scan: sequential EMA over T. One thread per (b, h-pair), half2 I/O.
// ---------------------------------------------------------------------------
__global__ __launch_bounds__(256)
void scan_kernel(const float* __restrict__ b1, const float* __restrict__ tau1,
                 const float* __restrict__ b2, const float* __restrict__ tau2)
{
    const int idx = blockIdx.x * blockDim.x + threadIdx.x;   // 0..16383
    const int h0  = (idx & 255) * 2;

    const float a1x = 1.0f / (1.0f + __expf(-tau1[h0]));
    const float a1y = 1.0f / (1.0f + __expf(-tau1[h0 + 1]));
    const float a2x = 1.0f / (1.0f + __expf(-tau2[h0]));
    const float a2y = 1.0f / (1.0f + __expf(-tau2[h0 + 1]));
    const float c1x = 1.0f - a1x, c1y = 1.0f - a1y;
    const float c2x = 1.0f - a2x, c2y = 1.0f - a2y;
    const float b1x = b1[h0], b1y = b1[h0 + 1];
    const float b2x = b2[h0], b2y = b2[h0 + 1];

    const __half2* d1p = (const __half2*)g_d1;
    const __half2* d2p = (const __half2*)g_d2;
    __half2* mp = (__half2*)g_m16;
    const int stride = BH_ / 2;   // 16384

    float d1vx = 0.f, d1vy = 0.f, d2vx = 0.f, d2vy = 0.f, memx = 0.f, memy = 0.f;

    #pragma unroll 1
    for (int t = 0; t < T_; t += 8) {
        __half2 i1[8], i2[8];
        #pragma unroll
        for (int u = 0; u < 8; ++u) {
            i1[u] = __ldcs(&d1p[(size_t)(t + u) * stride + idx]);
            i2[u] = __ldcs(&d2p[(size_t)(t + u) * stride + idx]);
        }
        #pragma unroll
        for (int u = 0; u < 8; ++u) {
            float2 f1 = __half22float2(i1[u]);
            float2 f2 = __half22float2(i2[u]);
            d1vx = a1x * d1vx + c1x * (f1.x + b1x);
            d1vy = a1y * d1vy + c1y * (f1.y + b1y);
            d2vx = a2x * d2vx + c2x * (f2.x + b2x);
            d2vy = a2y * d2vy + c2y * (f2.y + b2y);
            memx = 0.8f * memx + 0.2f * (d1vx + d2vx);
            memy = 0.8f * memy + 0.2f * (d1vy + d2vy);
            __stcs(&mp[(size_t)(t + u) * stride + idx], __floats2half2_rn(memx, memy));
        }
    }
}

// ---------------------------------------------------------------------------
// GEMM-2: out = sigmoid(mems @ wo^T + bo). 8 K64 chunks. Grid (512).
// ---------------------------------------------------------------------------
__global__ __launch_bounds__(256, 2)
void hmma_gemm2_kernel(const float* __restrict__ bo, float* __restrict__ out)
{
    extern __shared__ __align__(16) char smraw[];
    char* smem = smraw + ((1024 - (smem_u32(smraw) & 1023)) & 1023);
    const uint32_t sbase = smem_u32(smem);

    const int tid    = threadIdx.x;
    const int wid    = tid >> 5;
    const int lane   = tid & 31;
    const int warp_m = (wid & 3) * 32;
    const int warp_n = (wid >> 2) * 64;

    const int m0 = blockIdx.x * 128;

    auto issue_chunk = [&](int c) {
        const uint32_t sb = sbase + (c % 3) * STAGE_B;
        const int k1 = c * 64;
        cp_tile64<128>(sb,         g_m16, H_, m0, k1, tid);
        cp_tile64<128>(sb + OFF_W, g_wo,  H_, 0,  k1, tid);
        CP_COMMIT();
    };

    float acc[2][8][4];
    acc_zero(acc);

    issue_chunk(0);
    issue_chunk(1);

    #pragma unroll 1
    for (int c = 0; c < 8; ++c) {
        if (c < 7) { CP_WAIT1(); } else { CP_WAIT0(); }
        __syncthreads();
        if (c + 2 < 8) issue_chunk(c + 2);

        chunk_compute(sbase + (c % 3) * STAGE_B, warp_m, warp_n, lane, acc);
    }

    // Epilogue: bias + sigmoid; out[b,t,o], row m = t*B + b
    #pragma unroll
    for (int mt = 0; mt < 2; ++mt) {
        #pragma unroll
        for (int half = 0; half < 2; ++half) {
            const int m = m0 + warp_m + mt * 16 + (lane >> 2) + half * 8;
            const int t = m >> 6;           // / B_
            const int b = m & (B_ - 1);
            float* rowp = out + (size_t)b * (T_ * O_) + (size_t)t * O_ + warp_n;
            #pragma unroll
            for (int nt = 0; nt < 8; ++nt) {
                const int n = nt * 8 + (lane & 3) * 2;
                float v0 = half ? acc[mt][nt][2] : acc[mt][nt][0];
                float v1 = half ? acc[mt][nt][3] : acc[mt][nt][1];
                v0 += bo[warp_n + n];
                v1 += bo[warp_n + n + 1];
                v0 = 1.0f / (1.0f + __expf(-v0));
                v1 = 1.0f / (1.0f + __expf(-v1));
                *(float2*)(rowp + n) = make_float2(v0, v1);
            }
        }
    }
}

// ---------------------------------------------------------------------------
extern "C" void kernel_launch(void* const* d_in, const int* in_sizes, int n_in,
                              void* d_out, int out_size)
{
    const float* x    = (const float*)d_in[0];
    const float* w1   = (const float*)d_in[1];
    const float* b1   = (const float*)d_in[2];
    const float* tau1 = (const float*)d_in[3];
    const float* w2   = (const float*)d_in[4];
    const float* b2   = (const float*)d_in[5];
    const float* tau2 = (const float*)d_in[6];
    const float* wo   = (const float*)d_in[7];
    const float* bo   = (const float*)d_in[8];
    float* out = (float*)d_out;

    cudaFuncSetAttribute(hmma_gemm1_kernel,
                         cudaFuncAttributeMaxDynamicSharedMemorySize, SMEM_GEMM);
    cudaFuncSetAttribute(hmma_gemm2_kernel,
                         cudaFuncAttributeMaxDynamicSharedMemorySize, SMEM_GEMM);

    split_all_kernel<<<2048, 256>>>(x, w1, w2, wo);

    dim3 g1(M_ / 128, H_ / 128);          // 512 x 4
    hmma_gemm1_kernel<<<g1, 256, SMEM_GEMM>>>();

    scan_kernel<<<(BH_ / 2) / 256, 256>>>(b1, tau1, b2, tau2);

    hmma_gemm2_kernel<<<M_ / 128, 256, SMEM_GEMM>>>(bo, out);
}

// round 14
// speedup vs baseline: 1.5300x; 1.0117x over previous
#include <cuda_runtime.h>
#include <cuda_fp16.h>
#include <cstdint>

// Problem constants
#define B_    64
#define T_    1024
#define D_    512
#define H_    512
#define O_    128
#define HALF_ 256
#define M_    (B_ * T_)          // 65536
#define BH_   (B_ * H_)          // 32768

// ---------------------------------------------------------------------------
// Device-global scratch (all fp16 single-plane)
// ---------------------------------------------------------------------------
__device__ __half  g_d1[T_ * B_ * H_];     // [T,B,H] fp16
__device__ __half  g_d2[T_ * B_ * H_];     // [T,B,H] fp16
__device__ __half  g_x16[M_ * D_];         // x fp16
__device__ __half  g_w1[H_ * HALF_];       // w1 fp16
__device__ __half  g_w2[H_ * HALF_];       // w2 fp16
__device__ __half  g_wo[O_ * H_];          // wo fp16
__device__ __half  g_m16[T_ * B_ * H_];    // mems fp16, row m = t*B+b

// ---------------------------------------------------------------------------
// Helpers
// ---------------------------------------------------------------------------
__device__ __forceinline__ uint32_t smem_u32(const void* p) {
    uint32_t a;
    asm("{ .reg .u64 t; cvta.to.shared.u64 t, %1; cvt.u32.u64 %0, t; }"
        : "=r"(a) : "l"(p));
    return a;
}
__device__ __forceinline__ void ldsm4(uint32_t r[4], uint32_t addr) {
    asm volatile("ldmatrix.sync.aligned.m8n8.x4.shared.b16 {%0,%1,%2,%3}, [%4];"
        : "=r"(r[0]), "=r"(r[1]), "=r"(r[2]), "=r"(r[3]) : "r"(addr));
}
__device__ __forceinline__ void mma16816(float c[4], const uint32_t a[4],
                                         const uint32_t b0, const uint32_t b1) {
    asm volatile(
        "mma.sync.aligned.m16n8k16.row.col.f32.f16.f16.f32 "
        "{%0,%1,%2,%3}, {%4,%5,%6,%7}, {%8,%9}, {%0,%1,%2,%3};"
        : "+f"(c[0]), "+f"(c[1]), "+f"(c[2]), "+f"(c[3])
        : "r"(a[0]), "r"(a[1]), "r"(a[2]), "r"(a[3]), "r"(b0), "r"(b1));
}
__device__ __forceinline__ void cp16(uint32_t dst, const void* src) {
    asm volatile("cp.async.cg.shared.global [%0], [%1], 16;"
        :: "r"(dst), "l"(src) : "memory");
}
#define CP_COMMIT() asm volatile("cp.async.commit_group;" ::: "memory")
#define CP_WAIT0()  asm volatile("cp.async.wait_group 0;" ::: "memory")
#define CP_WAIT1()  asm volatile("cp.async.wait_group 1;" ::: "memory")

// 128-byte rows (64 fp16), SW128 swizzle
#define SW128(o)   ((o) ^ (((o) >> 3) & 0x70))

// cp.async an R x 64 fp16 tile (K-major global) into SW128 smem. 256 threads.
template <int R>
__device__ __forceinline__ void cp_tile64(uint32_t sbase,
                                          const __half* __restrict__ g,
                                          int ld, int row0, int k0, int tid)
{
    #pragma unroll
    for (int i = 0; i < (R * 8) / 256; ++i) {
        const int slot = tid + i * 256;
        const int r = slot >> 3;
        const int v = slot & 7;
        cp16(sbase + SW128((uint32_t)(r * 128 + v * 16)),
             g + (size_t)(row0 + r) * ld + k0 + v * 8);
    }
}

// ---------------------------------------------------------------------------
// Fused convert: x, w1, w2, wo -> single fp16 planes, one launch.
// __ldcs on fp32 source (read-once); NORMAL stores (re-read soon, keep in L2).
// ---------------------------------------------------------------------------
#define NXV  ((M_ * D_) / 4)
#define NWV  ((H_ * HALF_) / 4)
#define NOV  ((O_ * H_) / 4)

__device__ __forceinline__ void cvt_vec(const float* src, __half* dst, int i)
{
    float4 v = __ldcs(&((const float4*)src)[i]);
    float f[4] = {v.x, v.y, v.z, v.w};
    uint32_t p[2];
    #pragma unroll
    for (int j = 0; j < 2; ++j) {
        __half h0 = __float2half_rn(f[2*j]);
        __half h1 = __float2half_rn(f[2*j+1]);
        p[j] = (uint32_t)__half_as_ushort(h0) | ((uint32_t)__half_as_ushort(h1) << 16);
    }
    ((uint2*)dst)[i] = make_uint2(p[0], p[1]);
}

__global__ void split_all_kernel(const float* __restrict__ x,
                                 const float* __restrict__ w1,
                                 const float* __restrict__ w2,
                                 const float* __restrict__ wo)
{
    const int total = NXV + 2 * NWV + NOV;
    for (int i = blockIdx.x * blockDim.x + threadIdx.x; i < total;
         i += gridDim.x * blockDim.x) {
        if (i < NXV)                 cvt_vec(x,  g_x16, i);
        else if (i < NXV + NWV)      cvt_vec(w1, g_w1,  i - NXV);
        else if (i < NXV + 2 * NWV)  cvt_vec(w2, g_w2,  i - NXV - NWV);
        else                         cvt_vec(wo, g_wo,  i - NXV - 2 * NWV);
    }
}

// ---------------------------------------------------------------------------
// Shared GEMM geometry: CTA 128(m) x 128(n), 256 thr, 8 warps (4m x 2n),
// warp tile 32 x 64, K-chunk 64, 3-stage cp.async multistage, 2 CTAs/SM.
// Stage: A|W, each 128x64 fp16 = 16 KB -> 32 KB/stage, 96 KB total.
// ---------------------------------------------------------------------------
#define OFF_W   16384
#define STAGE_B 32768
#define SMEM_GEMM (1024 + 3 * STAGE_B)

// 1-term fp16 compute of one K64 chunk for warp tile 32x64.
__device__ __forceinline__ void chunk_compute(uint32_t sb, int warp_m, int warp_n,
                                              int lane, float acc[2][8][4])
{
    const uint32_t sA = sb, sW = sb + OFF_W;
    #pragma unroll
    for (int ks = 0; ks < 4; ++ks) {
        const int akb = ks * 32 + ((lane & 16) ? 16 : 0);
        uint32_t a[2][4];
        #pragma unroll
        for (int mt = 0; mt < 2; ++mt) {
            const int row = warp_m + mt * 16 + (lane & 15);
            ldsm4(a[mt], sA + SW128((uint32_t)(row * 128 + akb)));
        }
        const int bkb = ks * 32 + ((lane & 8) ? 16 : 0);
        uint32_t w[4][4];
        #pragma unroll
        for (int nt2 = 0; nt2 < 4; ++nt2) {
            const int brow = warp_n + nt2 * 16 + (lane & 7) + ((lane & 16) ? 8 : 0);
            ldsm4(w[nt2], sW + SW128((uint32_t)(brow * 128 + bkb)));
        }
        #pragma unroll
        for (int nt2 = 0; nt2 < 4; ++nt2)
            #pragma unroll
            for (int mt = 0; mt < 2; ++mt) {
                mma16816(acc[mt][nt2 * 2 + 0], a[mt], w[nt2][0], w[nt2][1]);
                mma16816(acc[mt][nt2 * 2 + 1], a[mt], w[nt2][2], w[nt2][3]);
            }
    }
}

__device__ __forceinline__ void acc_zero(float acc[2][8][4]) {
    #pragma unroll
    for (int a = 0; a < 2; ++a)
        #pragma unroll
        for (int b = 0; b < 8; ++b)
            #pragma unroll
            for (int c = 0; c < 4; ++c) acc[a][b][c] = 0.0f;
}

// ---------------------------------------------------------------------------
// GEMM-1: 8 K64 chunks (0-3: x[:256]@w1 -> d1, 4-7: x[256:]@w2 -> d2).
// Grid (512, 4). Outputs fp16.
// ---------------------------------------------------------------------------
__global__ __launch_bounds__(256, 2)
void hmma_gemm1_kernel()
{
    extern __shared__ __align__(16) char smraw[];
    char* smem = smraw + ((1024 - (smem_u32(smraw) & 1023)) & 1023);
    const uint32_t sbase = smem_u32(smem);

    const int tid    = threadIdx.x;
    const int wid    = tid >> 5;
    const int lane   = tid & 31;
    const int warp_m = (wid & 3) * 32;
    const int warp_n = (wid >> 2) * 64;

    const int m0 = blockIdx.x * 128;
    const int n0 = blockIdx.y * 128;

    auto issue_chunk = [&](int c) {
        const uint32_t sb = sbase + (c % 3) * STAGE_B;
        const __half* w = (c >= 4) ? g_w2 : g_w1;
        const int kx = c * 64;
        const int kw = (c & 3) * 64;
        cp_tile64<128>(sb,         g_x16, D_,    m0, kx, tid);
        cp_tile64<128>(sb + OFF_W, w,     HALF_, n0, kw, tid);
        CP_COMMIT();
    };

    float acc[2][8][4];
    acc_zero(acc);

    issue_chunk(0);
    issue_chunk(1);

    #pragma unroll 1
    for (int c = 0; c < 8; ++c) {
        if (c < 7) { CP_WAIT1(); } else { CP_WAIT0(); }
        __syncthreads();
        if (c + 2 < 8) issue_chunk(c + 2);

        chunk_compute(sbase + (c % 3) * STAGE_B, warp_m, warp_n, lane, acc);

        if (c == 3 || c == 7) {
            __half* dst = (c == 3) ? g_d1 : g_d2;
            #pragma unroll
            for (int mt = 0; mt < 2; ++mt) {
                #pragma unroll
                for (int half = 0; half < 2; ++half) {
                    const int m = m0 + warp_m + mt * 16 + (lane >> 2) + half * 8;
                    const int b = m >> 10;
                    const int t = m & (T_ - 1);
                    __half* rowp = dst + (size_t)t * BH_ + (size_t)b * H_ + n0 + warp_n;
                    #pragma unroll
                    for (int nt = 0; nt < 8; ++nt) {
                        const int n = nt * 8 + (lane & 3) * 2;
                        float v0 = half ? acc[mt][nt][2] : acc[mt][nt][0];
                        float v1 = half ? acc[mt][nt][3] : acc[mt][nt][1];
                        *(__half2*)(rowp + n) = __floats2half2_rn(v0, v1);
                    }
                }
            }
            acc_zero(acc);
        }
    }
}

// ---------------------------------------------------------------------------
// Scan: sequential EMA over T. One thread per (b, h-pair), half2 I/O.
// blockDim 64 -> 256 blocks so all 148 SMs participate.
// d1/d2 reads are streaming (__ldcs); mems store NORMAL (gemm2 re-reads it).
// ---------------------------------------------------------------------------
__global__ __launch_bounds__(64)
void scan_kernel(const float* __restrict__ b1, const float* __restrict__ tau1,
                 const float* __restrict__ b2, const float* __restrict__ tau2)
{
    const int idx = blockIdx.x * blockDim.x + threadIdx.x;   // 0..16383
    const int h0  = (idx & 255) * 2;

    const float a1x = 1.0f / (1.0f + __expf(-tau1[h0]));
    const float a1y = 1.0f / (1.0f + __expf(-tau1[h0 + 1]));
    const float a2x = 1.0f / (1.0f + __expf(-tau2[h0]));
    const float a2y = 1.0f / (1.0f + __expf(-tau2[h0 + 1]));
    const float c1x = 1.0f - a1x, c1y = 1.0f - a1y;
    const float c2x = 1.0f - a2x, c2y = 1.0f - a2y;
    const float b1x = b1[h0], b1y = b1[h0 + 1];
    const float b2x = b2[h0], b2y = b2[h0 + 1];

    const __half2* d1p = (const __half2*)g_d1;
    const __half2* d2p = (const __half2*)g_d2;
    __half2* mp = (__half2*)g_m16;
    const int stride = BH_ / 2;   // 16384

    float d1vx = 0.f, d1vy = 0.f, d2vx = 0.f, d2vy = 0.f, memx = 0.f, memy = 0.f;

    #pragma unroll 1
    for (int t = 0; t < T_; t += 8) {
        __half2 i1[8], i2[8];
        #pragma unroll
        for (int u = 0; u < 8; ++u) {
            i1[u] = __ldcs(&d1p[(size_t)(t + u) * stride + idx]);
            i2[u] = __ldcs(&d2p[(size_t)(t + u) * stride + idx]);
        }
        #pragma unroll
        for (int u = 0; u < 8; ++u) {
            float2 f1 = __half22float2(i1[u]);
            float2 f2 = __half22float2(i2[u]);
            d1vx = a1x * d1vx + c1x * (f1.x + b1x);
            d1vy = a1y * d1vy + c1y * (f1.y + b1y);
            d2vx = a2x * d2vx + c2x * (f2.x + b2x);
            d2vy = a2y * d2vy + c2y * (f2.y + b2y);
            memx = 0.8f * memx + 0.2f * (d1vx + d2vx);
            memy = 0.8f * memy + 0.2f * (d1vy + d2vy);
            mp[(size_t)(t + u) * stride + idx] = __floats2half2_rn(memx, memy);
        }
    }
}

// ---------------------------------------------------------------------------
// GEMM-2: out = sigmoid(mems @ wo^T + bo). 8 K64 chunks. Grid (512).
// ---------------------------------------------------------------------------
__global__ __launch_bounds__(256, 2)
void hmma_gemm2_kernel(const float* __restrict__ bo, float* __restrict__ out)
{
    extern __shared__ __align__(16) char smraw[];
    char* smem = smraw + ((1024 - (smem_u32(smraw) & 1023)) & 1023);
    const uint32_t sbase = smem_u32(smem);

    const int tid    = threadIdx.x;
    const int wid    = tid >> 5;
    const int lane   = tid & 31;
    const int warp_m = (wid & 3) * 32;
    const int warp_n = (wid >> 2) * 64;

    const int m0 = blockIdx.x * 128;

    auto issue_chunk = [&](int c) {
        const uint32_t sb = sbase + (c % 3) * STAGE_B;
        const int k1 = c * 64;
        cp_tile64<128>(sb,         g_m16, H_, m0, k1, tid);
        cp_tile64<128>(sb + OFF_W, g_wo,  H_, 0,  k1, tid);
        CP_COMMIT();
    };

    float acc[2][8][4];
    acc_zero(acc);

    issue_chunk(0);
    issue_chunk(1);

    #pragma unroll 1
    for (int c = 0; c < 8; ++c) {
        if (c < 7) { CP_WAIT1(); } else { CP_WAIT0(); }
        __syncthreads();
        if (c + 2 < 8) issue_chunk(c + 2);

        chunk_compute(sbase + (c % 3) * STAGE_B, warp_m, warp_n, lane, acc);
    }

    // Epilogue: bias + sigmoid; out[b,t,o], row m = t*B + b
    #pragma unroll
    for (int mt = 0; mt < 2; ++mt) {
        #pragma unroll
        for (int half = 0; half < 2; ++half) {
            const int m = m0 + warp_m + mt * 16 + (lane >> 2) + half * 8;
            const int t = m >> 6;           // / B_
            const int b = m & (B_ - 1);
            float* rowp = out + (size_t)b * (T_ * O_) + (size_t)t * O_ + warp_n;
            #pragma unroll
            for (int nt = 0; nt < 8; ++nt) {
                const int n = nt * 8 + (lane & 3) * 2;
                float v0 = half ? acc[mt][nt][2] : acc[mt][nt][0];
                float v1 = half ? acc[mt][nt][3] : acc[mt][nt][1];
                v0 += bo[warp_n + n];
                v1 += bo[warp_n + n + 1];
                v0 = 1.0f / (1.0f + __expf(-v0));
                v1 = 1.0f / (1.0f + __expf(-v1));
                *(float2*)(rowp + n) = make_float2(v0, v1);
            }
        }
    }
}

// ---------------------------------------------------------------------------
extern "C" void kernel_launch(void* const* d_in, const int* in_sizes, int n_in,
                              void* d_out, int out_size)
{
    const float* x    = (const float*)d_in[0];
    const float* w1   = (const float*)d_in[1];
    const float* b1   = (const float*)d_in[2];
    const float* tau1 = (const float*)d_in[3];
    const float* w2   = (const float*)d_in[4];
    const float* b2   = (const float*)d_in[5];
    const float* tau2 = (const float*)d_in[6];
    const float* wo   = (const float*)d_in[7];
    const float* bo   = (const float*)d_in[8];
    float* out = (float*)d_out;

    cudaFuncSetAttribute(hmma_gemm1_kernel,
                         cudaFuncAttributeMaxDynamicSharedMemorySize, SMEM_GEMM);
    cudaFuncSetAttribute(hmma_gemm2_kernel,
                         cudaFuncAttributeMaxDynamicSharedMemorySize, SMEM_GEMM);

    split_all_kernel<<<2048, 256>>>(x, w1, w2, wo);

    dim3 g1(M_ / 128, H_ / 128);          // 512 x 4
    hmma_gemm1_kernel<<<g1, 256, SMEM_GEMM>>>();

    scan_kernel<<<(BH_ / 2) / 64, 64>>>(b1, tau1, b2, tau2);

    hmma_gemm2_kernel<<<M_ / 128, 256, SMEM_GEMM>>>(bo, out);
}

// round 15
// speedup vs baseline: 1.5389x; 1.0058x over previous
#include <cuda_runtime.h>
#include <cuda_fp16.h>
#include <cstdint>

// Problem constants
#define B_    64
#define T_    1024
#define D_    512
#define H_    512
#define O_    128
#define HALF_ 256
#define M_    (B_ * T_)          // 65536
#define BH_   (B_ * H_)          // 32768

// ---------------------------------------------------------------------------
// Device-global scratch (all fp16 single-plane)
// ---------------------------------------------------------------------------
__device__ __half  g_d1[T_ * B_ * H_];     // [T,B,H] fp16
__device__ __half  g_d2[T_ * B_ * H_];     // [T,B,H] fp16
__device__ __half  g_x16[M_ * D_];         // x fp16
__device__ __half  g_w1[H_ * HALF_];       // w1 fp16
__device__ __half  g_w2[H_ * HALF_];       // w2 fp16
__device__ __half  g_wo[O_ * H_];          // wo fp16
__device__ __half  g_m16[T_ * B_ * H_];    // mems fp16, row m = t*B+b

// ---------------------------------------------------------------------------
// Helpers
// ---------------------------------------------------------------------------
__device__ __forceinline__ uint32_t smem_u32(const void* p) {
    uint32_t a;
    asm("{ .reg .u64 t; cvta.to.shared.u64 t, %1; cvt.u32.u64 %0, t; }"
        : "=r"(a) : "l"(p));
    return a;
}
__device__ __forceinline__ void ldsm4(uint32_t r[4], uint32_t addr) {
    asm volatile("ldmatrix.sync.aligned.m8n8.x4.shared.b16 {%0,%1,%2,%3}, [%4];"
        : "=r"(r[0]), "=r"(r[1]), "=r"(r[2]), "=r"(r[3]) : "r"(addr));
}
__device__ __forceinline__ void mma16816(float c[4], const uint32_t a[4],
                                         const uint32_t b0, const uint32_t b1) {
    asm volatile(
        "mma.sync.aligned.m16n8k16.row.col.f32.f16.f16.f32 "
        "{%0,%1,%2,%3}, {%4,%5,%6,%7}, {%8,%9}, {%0,%1,%2,%3};"
        : "+f"(c[0]), "+f"(c[1]), "+f"(c[2]), "+f"(c[3])
        : "r"(a[0]), "r"(a[1]), "r"(a[2]), "r"(a[3]), "r"(b0), "r"(b1));
}
__device__ __forceinline__ void cp16(uint32_t dst, const void* src) {
    asm volatile("cp.async.cg.shared.global [%0], [%1], 16;"
        :: "r"(dst), "l"(src) : "memory");
}
#define CP_COMMIT() asm volatile("cp.async.commit_group;" ::: "memory")
#define CP_WAIT0()  asm volatile("cp.async.wait_group 0;" ::: "memory")
#define CP_WAIT1()  asm volatile("cp.async.wait_group 1;" ::: "memory")

// 128-byte rows (64 fp16), SW128 swizzle
#define SW128(o)   ((o) ^ (((o) >> 3) & 0x70))

// cp.async an R x 64 fp16 tile (K-major global) into SW128 smem. 256 threads.
template <int R>
__device__ __forceinline__ void cp_tile64(uint32_t sbase,
                                          const __half* __restrict__ g,
                                          int ld, int row0, int k0, int tid)
{
    #pragma unroll
    for (int i = 0; i < (R * 8) / 256; ++i) {
        const int slot = tid + i * 256;
        const int r = slot >> 3;
        const int v = slot & 7;
        cp16(sbase + SW128((uint32_t)(r * 128 + v * 16)),
             g + (size_t)(row0 + r) * ld + k0 + v * 8);
    }
}

// ---------------------------------------------------------------------------
// Fused convert: x, w1, w2, wo -> single fp16 planes, one launch.
// ---------------------------------------------------------------------------
#define NXV  ((M_ * D_) / 4)
#define NWV  ((H_ * HALF_) / 4)
#define NOV  ((O_ * H_) / 4)

__device__ __forceinline__ void cvt_vec(const float* src, __half* dst, int i)
{
    float4 v = __ldcs(&((const float4*)src)[i]);
    float f[4] = {v.x, v.y, v.z, v.w};
    uint32_t p[2];
    #pragma unroll
    for (int j = 0; j < 2; ++j) {
        __half h0 = __float2half_rn(f[2*j]);
        __half h1 = __float2half_rn(f[2*j+1]);
        p[j] = (uint32_t)__half_as_ushort(h0) | ((uint32_t)__half_as_ushort(h1) << 16);
    }
    ((uint2*)dst)[i] = make_uint2(p[0], p[1]);
}

__global__ void split_all_kernel(const float* __restrict__ x,
                                 const float* __restrict__ w1,
                                 const float* __restrict__ w2,
                                 const float* __restrict__ wo)
{
    const int total = NXV + 2 * NWV + NOV;
    for (int i = blockIdx.x * blockDim.x + threadIdx.x; i < total;
         i += gridDim.x * blockDim.x) {
        if (i < NXV)                 cvt_vec(x,  g_x16, i);
        else if (i < NXV + NWV)      cvt_vec(w1, g_w1,  i - NXV);
        else if (i < NXV + 2 * NWV)  cvt_vec(w2, g_w2,  i - NXV - NWV);
        else                         cvt_vec(wo, g_wo,  i - NXV - 2 * NWV);
    }
}

// ---------------------------------------------------------------------------
// Shared GEMM geometry: CTA 128(m) x 128(n), 256 thr, 8 warps (4m x 2n),
// warp tile 32 x 64, K-chunk 64, 3-stage cp.async multistage, 2 CTAs/SM.
// Stage: A|W, each 128x64 fp16 = 16 KB -> 32 KB/stage, 96 KB total.
// ---------------------------------------------------------------------------
#define OFF_W   16384
#define STAGE_B 32768
#define SMEM_GEMM (1024 + 3 * STAGE_B)

// 1-term fp16 compute of one K64 chunk for warp tile 32x64.
__device__ __forceinline__ void chunk_compute(uint32_t sb, int warp_m, int warp_n,
                                              int lane, float acc[2][8][4])
{
    const uint32_t sA = sb, sW = sb + OFF_W;
    #pragma unroll
    for (int ks = 0; ks < 4; ++ks) {
        const int akb = ks * 32 + ((lane & 16) ? 16 : 0);
        uint32_t a[2][4];
        #pragma unroll
        for (int mt = 0; mt < 2; ++mt) {
            const int row = warp_m + mt * 16 + (lane & 15);
            ldsm4(a[mt], sA + SW128((uint32_t)(row * 128 + akb)));
        }
        const int bkb = ks * 32 + ((lane & 8) ? 16 : 0);
        uint32_t w[4][4];
        #pragma unroll
        for (int nt2 = 0; nt2 < 4; ++nt2) {
            const int brow = warp_n + nt2 * 16 + (lane & 7) + ((lane & 16) ? 8 : 0);
            ldsm4(w[nt2], sW + SW128((uint32_t)(brow * 128 + bkb)));
        }
        #pragma unroll
        for (int nt2 = 0; nt2 < 4; ++nt2)
            #pragma unroll
            for (int mt = 0; mt < 2; ++mt) {
                mma16816(acc[mt][nt2 * 2 + 0], a[mt], w[nt2][0], w[nt2][1]);
                mma16816(acc[mt][nt2 * 2 + 1], a[mt], w[nt2][2], w[nt2][3]);
            }
    }
}

__device__ __forceinline__ void acc_zero(float acc[2][8][4]) {
    #pragma unroll
    for (int a = 0; a < 2; ++a)
        #pragma unroll
        for (int b = 0; b < 8; ++b)
            #pragma unroll
            for (int c = 0; c < 4; ++c) acc[a][b][c] = 0.0f;
}

// ---------------------------------------------------------------------------
// GEMM-1: 8 K64 chunks (0-3: x[:256]@w1 -> d1, 4-7: x[256:]@w2 -> d2).
// Grid (4, 512) — n-tile varies FASTEST so each scheduling wave covers all 4
// n-tiles of ~74 m-tiles: every x tile is fetched once from DRAM and reused
// 4x from L2. Outputs fp16.
// ---------------------------------------------------------------------------
__global__ __launch_bounds__(256, 2)
void hmma_gemm1_kernel()
{
    extern __shared__ __align__(16) char smraw[];
    char* smem = smraw + ((1024 - (smem_u32(smraw) & 1023)) & 1023);
    const uint32_t sbase = smem_u32(smem);

    const int tid    = threadIdx.x;
    const int wid    = tid >> 5;
    const int lane   = tid & 31;
    const int warp_m = (wid & 3) * 32;
    const int warp_n = (wid >> 2) * 64;

    const int m0 = blockIdx.y * 128;      // 512 m-tiles
    const int n0 = blockIdx.x * 128;      // 4 n-tiles (fastest-varying)

    auto issue_chunk = [&](int c) {
        const uint32_t sb = sbase + (c % 3) * STAGE_B;
        const __half* w = (c >= 4) ? g_w2 : g_w1;
        const int kx = c * 64;
        const int kw = (c & 3) * 64;
        cp_tile64<128>(sb,         g_x16, D_,    m0, kx, tid);
        cp_tile64<128>(sb + OFF_W, w,     HALF_, n0, kw, tid);
        CP_COMMIT();
    };

    float acc[2][8][4];
    acc_zero(acc);

    issue_chunk(0);
    issue_chunk(1);

    #pragma unroll 1
    for (int c = 0; c < 8; ++c) {
        if (c < 7) { CP_WAIT1(); } else { CP_WAIT0(); }
        __syncthreads();
        if (c + 2 < 8) issue_chunk(c + 2);

        chunk_compute(sbase + (c % 3) * STAGE_B, warp_m, warp_n, lane, acc);

        if (c == 3 || c == 7) {
            __half* dst = (c == 3) ? g_d1 : g_d2;
            #pragma unroll
            for (int mt = 0; mt < 2; ++mt) {
                #pragma unroll
                for (int half = 0; half < 2; ++half) {
                    const int m = m0 + warp_m + mt * 16 + (lane >> 2) + half * 8;
                    const int b = m >> 10;
                    const int t = m & (T_ - 1);
                    __half* rowp = dst + (size_t)t * BH_ + (size_t)b * H_ + n0 + warp_n;
                    #pragma unroll
                    for (int nt = 0; nt < 8; ++nt) {
                        const int n = nt * 8 + (lane & 3) * 2;
                        float v0 = half ? acc[mt][nt][2] : acc[mt][nt][0];
                        float v1 = half ? acc[mt][nt][3] : acc[mt][nt][1];
                        *(__half2*)(rowp + n) = __floats2half2_rn(v0, v1);
                    }
                }
            }
            acc_zero(acc);
        }
    }
}

// ---------------------------------------------------------------------------
// Scan: sequential EMA over T. One thread per (b, h-pair), half2 I/O.
// ---------------------------------------------------------------------------
__global__ __launch_bounds__(64)
void scan_kernel(const float* __restrict__ b1, const float* __restrict__ tau1,
                 const float* __restrict__ b2, const float* __restrict__ tau2)
{
    const int idx = blockIdx.x * blockDim.x + threadIdx.x;   // 0..16383
    const int h0  = (idx & 255) * 2;

    const float a1x = 1.0f / (1.0f + __expf(-tau1[h0]));
    const float a1y = 1.0f / (1.0f + __expf(-tau1[h0 + 1]));
    const float a2x = 1.0f / (1.0f + __expf(-tau2[h0]));
    const float a2y = 1.0f / (1.0f + __expf(-tau2[h0 + 1]));
    const float c1x = 1.0f - a1x, c1y = 1.0f - a1y;
    const float c2x = 1.0f - a2x, c2y = 1.0f - a2y;
    const float b1x = b1[h0], b1y = b1[h0 + 1];
    const float b2x = b2[h0], b2y = b2[h0 + 1];

    const __half2* d1p = (const __half2*)g_d1;
    const __half2* d2p = (const __half2*)g_d2;
    __half2* mp = (__half2*)g_m16;
    const int stride = BH_ / 2;   // 16384

    float d1vx = 0.f, d1vy = 0.f, d2vx = 0.f, d2vy = 0.f, memx = 0.f, memy = 0.f;

    #pragma unroll 1
    for (int t = 0; t < T_; t += 8) {
        __half2 i1[8], i2[8];
        #pragma unroll
        for (int u = 0; u < 8; ++u) {
            i1[u] = __ldcs(&d1p[(size_t)(t + u) * stride + idx]);
            i2[u] = __ldcs(&d2p[(size_t)(t + u) * stride + idx]);
        }
        #pragma unroll
        for (int u = 0; u < 8; ++u) {
            float2 f1 = __half22float2(i1[u]);
            float2 f2 = __half22float2(i2[u]);
            d1vx = a1x * d1vx + c1x * (f1.x + b1x);
            d1vy = a1y * d1vy + c1y * (f1.y + b1y);
            d2vx = a2x * d2vx + c2x * (f2.x + b2x);
            d2vy = a2y * d2vy + c2y * (f2.y + b2y);
            memx = 0.8f * memx + 0.2f * (d1vx + d2vx);
            memy = 0.8f * memy + 0.2f * (d1vy + d2vy);
            mp[(size_t)(t + u) * stride + idx] = __floats2half2_rn(memx, memy);
        }
    }
}

// ---------------------------------------------------------------------------
// GEMM-2: out = sigmoid(mems @ wo^T + bo). 8 K64 chunks. Grid (512).
// ---------------------------------------------------------------------------
__global__ __launch_bounds__(256, 2)
void hmma_gemm2_kernel(const float* __restrict__ bo, float* __restrict__ out)
{
    extern __shared__ __align__(16) char smraw[];
    char* smem = smraw + ((1024 - (smem_u32(smraw) & 1023)) & 1023);
    const uint32_t sbase = smem_u32(smem);

    const int tid    = threadIdx.x;
    const int wid    = tid >> 5;
    const int lane   = tid & 31;
    const int warp_m = (wid & 3) * 32;
    const int warp_n = (wid >> 2) * 64;

    const int m0 = blockIdx.x * 128;

    auto issue_chunk = [&](int c) {
        const uint32_t sb = sbase + (c % 3) * STAGE_B;
        const int k1 = c * 64;
        cp_tile64<128>(sb,         g_m16, H_, m0, k1, tid);
        cp_tile64<128>(sb + OFF_W, g_wo,  H_, 0,  k1, tid);
        CP_COMMIT();
    };

    float acc[2][8][4];
    acc_zero(acc);

    issue_chunk(0);
    issue_chunk(1);

    #pragma unroll 1
    for (int c = 0; c < 8; ++c) {
        if (c < 7) { CP_WAIT1(); } else { CP_WAIT0(); }
        __syncthreads();
        if (c + 2 < 8) issue_chunk(c + 2);

        chunk_compute(sbase + (c % 3) * STAGE_B, warp_m, warp_n, lane, acc);
    }

    // Epilogue: bias + sigmoid; out[b,t,o], row m = t*B + b
    #pragma unroll
    for (int mt = 0; mt < 2; ++mt) {
        #pragma unroll
        for (int half = 0; half < 2; ++half) {
            const int m = m0 + warp_m + mt * 16 + (lane >> 2) + half * 8;
            const int t = m >> 6;           // / B_
            const int b = m & (B_ - 1);
            float* rowp = out + (size_t)b * (T_ * O_) + (size_t)t * O_ + warp_n;
            #pragma unroll
            for (int nt = 0; nt < 8; ++nt) {
                const int n = nt * 8 + (lane & 3) * 2;
                float v0 = half ? acc[mt][nt][2] : acc[mt][nt][0];
                float v1 = half ? acc[mt][nt][3] : acc[mt][nt][1];
                v0 += bo[warp_n + n];
                v1 += bo[warp_n + n + 1];
                v0 = 1.0f / (1.0f + __expf(-v0));
                v1 = 1.0f / (1.0f + __expf(-v1));
                *(float2*)(rowp + n) = make_float2(v0, v1);
            }
        }
    }
}

// ---------------------------------------------------------------------------
extern "C" void kernel_launch(void* const* d_in, const int* in_sizes, int n_in,
                              void* d_out, int out_size)
{
    const float* x    = (const float*)d_in[0];
    const float* w1   = (const float*)d_in[1];
    const float* b1   = (const float*)d_in[2];
    const float* tau1 = (const float*)d_in[3];
    const float* w2   = (const float*)d_in[4];
    const float* b2   = (const float*)d_in[5];
    const float* tau2 = (const float*)d_in[6];
    const float* wo   = (const float*)d_in[7];
    const float* bo   = (const float*)d_in[8];
    float* out = (float*)d_out;

    cudaFuncSetAttribute(hmma_gemm1_kernel,
                         cudaFuncAttributeMaxDynamicSharedMemorySize, SMEM_GEMM);
    cudaFuncSetAttribute(hmma_gemm2_kernel,
                         cudaFuncAttributeMaxDynamicSharedMemorySize, SMEM_GEMM);

    split_all_kernel<<<2048, 256>>>(x, w1, w2, wo);

    dim3 g1(H_ / 128, M_ / 128);          // (4, 512): n-tile fastest
    hmma_gemm1_kernel<<<g1, 256, SMEM_GEMM>>>();

    scan_kernel<<<(BH_ / 2) / 64, 64>>>(b1, tau1, b2, tau2);

    hmma_gemm2_kernel<<<M_ / 128, 256, SMEM_GEMM>>>(bo, out);
}

// round 16
// speedup vs baseline: 2.1746x; 1.4131x over previous
#include <cuda_runtime.h>
#include <cuda_fp16.h>
#include <cstdint>

// Problem constants
#define B_    64
#define T_    1024
#define D_    512
#define H_    512
#define O_    128
#define HALF_ 256
#define M_    (B_ * T_)          // 65536
#define BH_   (B_ * H_)          // 32768

// ---------------------------------------------------------------------------
// Device-global scratch
// ---------------------------------------------------------------------------
__device__ __half  g_x16[M_ * D_];         // x fp16
__device__ __half  g_w1[H_ * HALF_];       // w1 fp16
__device__ __half  g_w2[H_ * HALF_];       // w2 fp16
__device__ __half  g_wo[O_ * H_];          // wo fp16
__device__ __half  g_m16[T_ * B_ * H_];    // mems fp16, row m = t*B+b
// Per-CTA d1/d2 scratch ring: 256 CTAs x 2 x 128t x 128h fp16 = 16 MB.
// Each CTA reuses its own 64 KB slot every t-chunk -> stays L2-resident.
__device__ __half  g_ring[256 * 2 * 128 * 128];

// ---------------------------------------------------------------------------
// Helpers
// ---------------------------------------------------------------------------
__device__ __forceinline__ uint32_t smem_u32(const void* p) {
    uint32_t a;
    asm("{ .reg .u64 t; cvta.to.shared.u64 t, %1; cvt.u32.u64 %0, t; }"
        : "=r"(a) : "l"(p));
    return a;
}
__device__ __forceinline__ void ldsm4(uint32_t r[4], uint32_t addr) {
    asm volatile("ldmatrix.sync.aligned.m8n8.x4.shared.b16 {%0,%1,%2,%3}, [%4];"
        : "=r"(r[0]), "=r"(r[1]), "=r"(r[2]), "=r"(r[3]) : "r"(addr));
}
__device__ __forceinline__ void mma16816(float c[4], const uint32_t a[4],
                                         const uint32_t b0, const uint32_t b1) {
    asm volatile(
        "mma.sync.aligned.m16n8k16.row.col.f32.f16.f16.f32 "
        "{%0,%1,%2,%3}, {%4,%5,%6,%7}, {%8,%9}, {%0,%1,%2,%3};"
        : "+f"(c[0]), "+f"(c[1]), "+f"(c[2]), "+f"(c[3])
        : "r"(a[0]), "r"(a[1]), "r"(a[2]), "r"(a[3]), "r"(b0), "r"(b1));
}
__device__ __forceinline__ void cp16(uint32_t dst, const void* src) {
    asm volatile("cp.async.cg.shared.global [%0], [%1], 16;"
        :: "r"(dst), "l"(src) : "memory");
}
#define CP_COMMIT() asm volatile("cp.async.commit_group;" ::: "memory")
#define CP_WAIT0()  asm volatile("cp.async.wait_group 0;" ::: "memory")
#define CP_WAIT1()  asm volatile("cp.async.wait_group 1;" ::: "memory")

// 128-byte rows (64 fp16), SW128 swizzle
#define SW128(o)   ((o) ^ (((o) >> 3) & 0x70))

// cp.async an R x 64 fp16 tile (K-major global) into SW128 smem. 256 threads.
template <int R>
__device__ __forceinline__ void cp_tile64(uint32_t sbase,
                                          const __half* __restrict__ g,
                                          int ld, int row0, int k0, int tid)
{
    #pragma unroll
    for (int i = 0; i < (R * 8) / 256; ++i) {
        const int slot = tid + i * 256;
        const int r = slot >> 3;
        const int v = slot & 7;
        cp16(sbase + SW128((uint32_t)(r * 128 + v * 16)),
             g + (size_t)(row0 + r) * ld + k0 + v * 8);
    }
}

// ---------------------------------------------------------------------------
// Fused convert: x, w1, w2, wo -> single fp16 planes, one launch.
// ---------------------------------------------------------------------------
#define NXV  ((M_ * D_) / 4)
#define NWV  ((H_ * HALF_) / 4)
#define NOV  ((O_ * H_) / 4)

__device__ __forceinline__ void cvt_vec(const float* src, __half* dst, int i)
{
    float4 v = __ldcs(&((const float4*)src)[i]);
    float f[4] = {v.x, v.y, v.z, v.w};
    uint32_t p[2];
    #pragma unroll
    for (int j = 0; j < 2; ++j) {
        __half h0 = __float2half_rn(f[2*j]);
        __half h1 = __float2half_rn(f[2*j+1]);
        p[j] = (uint32_t)__half_as_ushort(h0) | ((uint32_t)__half_as_ushort(h1) << 16);
    }
    ((uint2*)dst)[i] = make_uint2(p[0], p[1]);
}

__global__ void split_all_kernel(const float* __restrict__ x,
                                 const float* __restrict__ w1,
                                 const float* __restrict__ w2,
                                 const float* __restrict__ wo)
{
    const int total = NXV + 2 * NWV + NOV;
    for (int i = blockIdx.x * blockDim.x + threadIdx.x; i < total;
         i += gridDim.x * blockDim.x) {
        if (i < NXV)                 cvt_vec(x,  g_x16, i);
        else if (i < NXV + NWV)      cvt_vec(w1, g_w1,  i - NXV);
        else if (i < NXV + 2 * NWV)  cvt_vec(w2, g_w2,  i - NXV - NWV);
        else                         cvt_vec(wo, g_wo,  i - NXV - 2 * NWV);
    }
}

// ---------------------------------------------------------------------------
// GEMM geometry: CTA 128(m) x 128(n), 256 thr, 8 warps (4m x 2n),
// warp tile 32 x 64, K-chunk 64, 3-stage cp.async multistage, 2 CTAs/SM.
// Stage: A|W, each 128x64 fp16 = 16 KB -> 32 KB/stage, 96 KB total.
// Fused kernel adds scan coeff/state smem (4.5 KB).
// ---------------------------------------------------------------------------
#define OFF_W   16384
#define STAGE_B 32768
#define SCAN_SMEM (9 * 128 * 4)           // 6 coeff + 3 state rows of 128 f32
#define SMEM_FUSED (1024 + 3 * STAGE_B + SCAN_SMEM)
#define SMEM_GEMM  (1024 + 3 * STAGE_B)

// 1-term fp16 compute of one K64 chunk for warp tile 32x64.
__device__ __forceinline__ void chunk_compute(uint32_t sb, int warp_m, int warp_n,
                                              int lane, float acc[2][8][4])
{
    const uint32_t sA = sb, sW = sb + OFF_W;
    #pragma unroll
    for (int ks = 0; ks < 4; ++ks) {
        const int akb = ks * 32 + ((lane & 16) ? 16 : 0);
        uint32_t a[2][4];
        #pragma unroll
        for (int mt = 0; mt < 2; ++mt) {
            const int row = warp_m + mt * 16 + (lane & 15);
            ldsm4(a[mt], sA + SW128((uint32_t)(row * 128 + akb)));
        }
        const int bkb = ks * 32 + ((lane & 8) ? 16 : 0);
        uint32_t w[4][4];
        #pragma unroll
        for (int nt2 = 0; nt2 < 4; ++nt2) {
            const int brow = warp_n + nt2 * 16 + (lane & 7) + ((lane & 16) ? 8 : 0);
            ldsm4(w[nt2], sW + SW128((uint32_t)(brow * 128 + bkb)));
        }
        #pragma unroll
        for (int nt2 = 0; nt2 < 4; ++nt2)
            #pragma unroll
            for (int mt = 0; mt < 2; ++mt) {
                mma16816(acc[mt][nt2 * 2 + 0], a[mt], w[nt2][0], w[nt2][1]);
                mma16816(acc[mt][nt2 * 2 + 1], a[mt], w[nt2][2], w[nt2][3]);
            }
    }
}

__device__ __forceinline__ void acc_zero(float acc[2][8][4]) {
    #pragma unroll
    for (int a = 0; a < 2; ++a)
        #pragma unroll
        for (int b = 0; b < 8; ++b)
            #pragma unroll
            for (int c = 0; c < 4; ++c) acc[a][b][c] = 0.0f;
}

// Write acc tile (fp16) into a 128x128 ring slot (row = t_local, col = h_local).
__device__ __forceinline__ void acc_to_ring(float acc[2][8][4], __half* ring,
                                            int warp_m, int warp_n, int lane)
{
    #pragma unroll
    for (int mt = 0; mt < 2; ++mt) {
        #pragma unroll
        for (int half = 0; half < 2; ++half) {
            const int tl = warp_m + mt * 16 + (lane >> 2) + half * 8;
            __half* rowp = ring + tl * 128 + warp_n;
            #pragma unroll
            for (int nt = 0; nt < 8; ++nt) {
                const int n = nt * 8 + (lane & 3) * 2;
                float v0 = half ? acc[mt][nt][2] : acc[mt][nt][0];
                float v1 = half ? acc[mt][nt][3] : acc[mt][nt][1];
                *(__half2*)(rowp + n) = __floats2half2_rn(v0, v1);
            }
        }
    }
}

// ---------------------------------------------------------------------------
// Fused GEMM-1 + scan. Grid (4 n-tiles, 64 b), 256 thr, 2 CTAs/SM = 1 wave.
// Per CTA: 8 t-chunks x (4 w1-chunks -> ring[0], 4 w2-chunks -> ring[1],
// then 128-step EMA scan from L2 ring, state carried in smem).
// ---------------------------------------------------------------------------
__global__ __launch_bounds__(256, 2)
void fused_gemm1_scan_kernel(const float* __restrict__ b1,
                             const float* __restrict__ tau1,
                             const float* __restrict__ b2,
                             const float* __restrict__ tau2)
{
    extern __shared__ __align__(16) char smraw[];
    char* smem = smraw + ((1024 - (smem_u32(smraw) & 1023)) & 1023);
    const uint32_t sbase = smem_u32(smem);
    float* s_scan = (float*)(smem + 3 * STAGE_B);   // [9][128]

    const int tid    = threadIdx.x;
    const int wid    = tid >> 5;
    const int lane   = tid & 31;
    const int warp_m = (wid & 3) * 32;
    const int warp_n = (wid >> 2) * 64;

    const int n0  = blockIdx.x * 128;     // 4 n-tiles (fastest)
    const int b   = blockIdx.y;           // 64 batches
    const int cta = b * 4 + blockIdx.x;   // 0..255

    __half* ring1 = g_ring + (size_t)(cta * 2 + 0) * (128 * 128);
    __half* ring2 = g_ring + (size_t)(cta * 2 + 1) * (128 * 128);

    // Init scan coeffs + zero states (threads 0-127, one h column each).
    if (tid < 128) {
        const int h = n0 + tid;
        const float a1 = 1.0f / (1.0f + __expf(-tau1[h]));
        const float a2 = 1.0f / (1.0f + __expf(-tau2[h]));
        s_scan[0 * 128 + tid] = a1;
        s_scan[1 * 128 + tid] = (1.0f - a1);
        s_scan[2 * 128 + tid] = b1[h];
        s_scan[3 * 128 + tid] = a2;
        s_scan[4 * 128 + tid] = (1.0f - a2);
        s_scan[5 * 128 + tid] = b2[h];
        s_scan[6 * 128 + tid] = 0.0f;     // d1 state
        s_scan[7 * 128 + tid] = 0.0f;     // d2 state
        s_scan[8 * 128 + tid] = 0.0f;     // mem state
    }

    auto issue_chunk = [&](int cc) {
        const uint32_t sb = sbase + (cc % 3) * STAGE_B;
        const int tc = cc >> 3;
        const int p  = cc & 7;
        const __half* w = (p >= 4) ? g_w2 : g_w1;
        const int kx = (p & 3) * 64 + ((p >= 4) ? HALF_ : 0);
        const int kw = (p & 3) * 64;
        const int m0 = b * T_ + tc * 128;
        cp_tile64<128>(sb,         g_x16, D_,    m0, kx, tid);
        cp_tile64<128>(sb + OFF_W, w,     HALF_, n0, kw, tid);
        CP_COMMIT();
    };

    float acc[2][8][4];
    acc_zero(acc);

    issue_chunk(0);
    issue_chunk(1);

    #pragma unroll 1
    for (int cc = 0; cc < 64; ++cc) {
        if (cc < 63) { CP_WAIT1(); } else { CP_WAIT0(); }
        __syncthreads();
        if (cc + 2 < 64) issue_chunk(cc + 2);

        chunk_compute(sbase + (cc % 3) * STAGE_B, warp_m, warp_n, lane, acc);

        const int p = cc & 7;
        if (p == 3) {
            acc_to_ring(acc, ring1, warp_m, warp_n, lane);
            acc_zero(acc);
        } else if (p == 7) {
            acc_to_ring(acc, ring2, warp_m, warp_n, lane);
            acc_zero(acc);
            __syncthreads();   // ring tiles visible to scan threads

            // Scan 128 t-steps for this t-chunk (threads 0-127, col = tid).
            if (tid < 128) {
                const int tc = cc >> 3;
                const float a1  = s_scan[0 * 128 + tid];
                const float c1  = s_scan[1 * 128 + tid];
                const float bb1 = s_scan[2 * 128 + tid];
                const float a2  = s_scan[3 * 128 + tid];
                const float c2  = s_scan[4 * 128 + tid];
                const float bb2 = s_scan[5 * 128 + tid];
                float d1v = s_scan[6 * 128 + tid];
                float d2v = s_scan[7 * 128 + tid];
                float mv  = s_scan[8 * 128 + tid];
                #pragma unroll 1
                for (int tb = 0; tb < 128; tb += 8) {
                    __half i1[8], i2[8];
                    #pragma unroll
                    for (int u = 0; u < 8; ++u) {
                        i1[u] = ring1[(tb + u) * 128 + tid];
                        i2[u] = ring2[(tb + u) * 128 + tid];
                    }
                    #pragma unroll
                    for (int u = 0; u < 8; ++u) {
                        d1v = a1 * d1v + c1 * (__half2float(i1[u]) + bb1);
                        d2v = a2 * d2v + c2 * (__half2float(i2[u]) + bb2);
                        mv  = 0.8f * mv + 0.2f * (d1v + d2v);
                        const int tg = tc * 128 + tb + u;
                        g_m16[((size_t)tg * B_ + b) * H_ + n0 + tid] =
                            __float2half_rn(mv);
                    }
                }
                s_scan[6 * 128 + tid] = d1v;
                s_scan[7 * 128 + tid] = d2v;
                s_scan[8 * 128 + tid] = mv;
            }
        }
    }
}

// ---------------------------------------------------------------------------
// GEMM-2: out = sigmoid(mems @ wo^T + bo). 8 K64 chunks. Grid (512).
// ---------------------------------------------------------------------------
__global__ __launch_bounds__(256, 2)
void hmma_gemm2_kernel(const float* __restrict__ bo, float* __restrict__ out)
{
    extern __shared__ __align__(16) char smraw[];
    char* smem = smraw + ((1024 - (smem_u32(smraw) & 1023)) & 1023);
    const uint32_t sbase = smem_u32(smem);

    const int tid    = threadIdx.x;
    const int wid    = tid >> 5;
    const int lane   = tid & 31;
    const int warp_m = (wid & 3) * 32;
    const int warp_n = (wid >> 2) * 64;

    const int m0 = blockIdx.x * 128;

    auto issue_chunk = [&](int c) {
        const uint32_t sb = sbase + (c % 3) * STAGE_B;
        const int k1 = c * 64;
        cp_tile64<128>(sb,         g_m16, H_, m0, k1, tid);
        cp_tile64<128>(sb + OFF_W, g_wo,  H_, 0,  k1, tid);
        CP_COMMIT();
    };

    float acc[2][8][4];
    acc_zero(acc);

    issue_chunk(0);
    issue_chunk(1);

    #pragma unroll 1
    for (int c = 0; c < 8; ++c) {
        if (c < 7) { CP_WAIT1(); } else { CP_WAIT0(); }
        __syncthreads();
        if (c + 2 < 8) issue_chunk(c + 2);

        chunk_compute(sbase + (c % 3) * STAGE_B, warp_m, warp_n, lane, acc);
    }

    // Epilogue: bias + sigmoid; out[b,t,o], row m = t*B + b
    #pragma unroll
    for (int mt = 0; mt < 2; ++mt) {
        #pragma unroll
        for (int half = 0; half < 2; ++half) {
            const int m = m0 + warp_m + mt * 16 + (lane >> 2) + half * 8;
            const int t = m >> 6;           // / B_
            const int b = m & (B_ - 1);
            float* rowp = out + (size_t)b * (T_ * O_) + (size_t)t * O_ + warp_n;
            #pragma unroll
            for (int nt = 0; nt < 8; ++nt) {
                const int n = nt * 8 + (lane & 3) * 2;
                float v0 = half ? acc[mt][nt][2] : acc[mt][nt][0];
                float v1 = half ? acc[mt][nt][3] : acc[mt][nt][1];
                v0 += bo[warp_n + n];
                v1 += bo[warp_n + n + 1];
                v0 = 1.0f / (1.0f + __expf(-v0));
                v1 = 1.0f / (1.0f + __expf(-v1));
                *(float2*)(rowp + n) = make_float2(v0, v1);
            }
        }
    }
}

// ---------------------------------------------------------------------------
extern "C" void kernel_launch(void* const* d_in, const int* in_sizes, int n_in,
                              void* d_out, int out_size)
{
    const float* x    = (const float*)d_in[0];
    const float* w1   = (const float*)d_in[1];
    const float* b1   = (const float*)d_in[2];
    const float* tau1 = (const float*)d_in[3];
    const float* w2   = (const float*)d_in[4];
    const float* b2   = (const float*)d_in[5];
    const float* tau2 = (const float*)d_in[6];
    const float* wo   = (const float*)d_in[7];
    const float* bo   = (const float*)d_in[8];
    float* out = (float*)d_out;

    cudaFuncSetAttribute(fused_gemm1_scan_kernel,
                         cudaFuncAttributeMaxDynamicSharedMemorySize, SMEM_FUSED);
    cudaFuncSetAttribute(hmma_gemm2_kernel,
                         cudaFuncAttributeMaxDynamicSharedMemorySize, SMEM_GEMM);

    split_all_kernel<<<2048, 256>>>(x, w1, w2, wo);

    dim3 g1(H_ / 128, B_);                // (4, 64) = 256 CTAs, one wave
    fused_gemm1_scan_kernel<<<g1, 256, SMEM_FUSED>>>(b1, tau1, b2, tau2);

    hmma_gemm2_kernel<<<M_ / 128, 256, SMEM_GEMM>>>(bo, out);
}

// round 17
// speedup vs baseline: 2.1779x; 1.0015x over previous
#include <cuda_runtime.h>
#include <cuda_fp16.h>
#include <cstdint>

// Problem constants
#define B_    64
#define T_    1024
#define D_    512
#define H_    512
#define O_    128
#define HALF_ 256
#define M_    (B_ * T_)          // 65536
#define BH_   (B_ * H_)          // 32768

// ---------------------------------------------------------------------------
// Device-global scratch
// ---------------------------------------------------------------------------
__device__ __half  g_x16[M_ * D_];         // x fp16
__device__ __half  g_w1[H_ * HALF_];       // w1 fp16
__device__ __half  g_w2[H_ * HALF_];       // w2 fp16
__device__ __half  g_wo[O_ * H_];          // wo fp16
__device__ __half  g_m16[T_ * B_ * H_];    // mems fp16, row m = t*B+b
// Per-CTA d1/d2 scratch ring: 256 CTAs x 2 x 128t x 128h fp16 = 16 MB (L2-resident).
__device__ __half  g_ring[256 * 2 * 128 * 128];

// ---------------------------------------------------------------------------
// Helpers
// ---------------------------------------------------------------------------
__device__ __forceinline__ uint32_t smem_u32(const void* p) {
    uint32_t a;
    asm("{ .reg .u64 t; cvta.to.shared.u64 t, %1; cvt.u32.u64 %0, t; }"
        : "=r"(a) : "l"(p));
    return a;
}
__device__ __forceinline__ void ldsm4(uint32_t r[4], uint32_t addr) {
    asm volatile("ldmatrix.sync.aligned.m8n8.x4.shared.b16 {%0,%1,%2,%3}, [%4];"
        : "=r"(r[0]), "=r"(r[1]), "=r"(r[2]), "=r"(r[3]) : "r"(addr));
}
__device__ __forceinline__ void mma16816(float c[4], const uint32_t a[4],
                                         const uint32_t b0, const uint32_t b1) {
    asm volatile(
        "mma.sync.aligned.m16n8k16.row.col.f32.f16.f16.f32 "
        "{%0,%1,%2,%3}, {%4,%5,%6,%7}, {%8,%9}, {%0,%1,%2,%3};"
        : "+f"(c[0]), "+f"(c[1]), "+f"(c[2]), "+f"(c[3])
        : "r"(a[0]), "r"(a[1]), "r"(a[2]), "r"(a[3]), "r"(b0), "r"(b1));
}
__device__ __forceinline__ void cp16(uint32_t dst, const void* src) {
    asm volatile("cp.async.cg.shared.global [%0], [%1], 16;"
        :: "r"(dst), "l"(src) : "memory");
}
#define CP_COMMIT() asm volatile("cp.async.commit_group;" ::: "memory")
#define CP_WAIT0()  asm volatile("cp.async.wait_group 0;" ::: "memory")
#define CP_WAIT1()  asm volatile("cp.async.wait_group 1;" ::: "memory")

// 128-byte rows (64 fp16), SW128 swizzle
#define SW128(o)   ((o) ^ (((o) >> 3) & 0x70))

// cp.async an R x 64 fp16 tile (K-major global) into SW128 smem. 256 threads.
template <int R>
__device__ __forceinline__ void cp_tile64(uint32_t sbase,
                                          const __half* __restrict__ g,
                                          int ld, int row0, int k0, int tid)
{
    #pragma unroll
    for (int i = 0; i < (R * 8) / 256; ++i) {
        const int slot = tid + i * 256;
        const int r = slot >> 3;
        const int v = slot & 7;
        cp16(sbase + SW128((uint32_t)(r * 128 + v * 16)),
             g + (size_t)(row0 + r) * ld + k0 + v * 8);
    }
}

// ---------------------------------------------------------------------------
// Fused convert: x, w1, w2, wo -> single fp16 planes, one launch.
// ---------------------------------------------------------------------------
#define NXV  ((M_ * D_) / 4)
#define NWV  ((H_ * HALF_) / 4)
#define NOV  ((O_ * H_) / 4)

__device__ __forceinline__ void cvt_vec(const float* src, __half* dst, int i)
{
    float4 v = __ldcs(&((const float4*)src)[i]);
    float f[4] = {v.x, v.y, v.z, v.w};
    uint32_t p[2];
    #pragma unroll
    for (int j = 0; j < 2; ++j) {
        __half h0 = __float2half_rn(f[2*j]);
        __half h1 = __float2half_rn(f[2*j+1]);
        p[j] = (uint32_t)__half_as_ushort(h0) | ((uint32_t)__half_as_ushort(h1) << 16);
    }
    ((uint2*)dst)[i] = make_uint2(p[0], p[1]);
}

__global__ void split_all_kernel(const float* __restrict__ x,
                                 const float* __restrict__ w1,
                                 const float* __restrict__ w2,
                                 const float* __restrict__ wo)
{
    const int total = NXV + 2 * NWV + NOV;
    for (int i = blockIdx.x * blockDim.x + threadIdx.x; i < total;
         i += gridDim.x * blockDim.x) {
        if (i < NXV)                 cvt_vec(x,  g_x16, i);
        else if (i < NXV + NWV)      cvt_vec(w1, g_w1,  i - NXV);
        else if (i < NXV + 2 * NWV)  cvt_vec(w2, g_w2,  i - NXV - NWV);
        else                         cvt_vec(wo, g_wo,  i - NXV - 2 * NWV);
    }
}

// ---------------------------------------------------------------------------
// GEMM geometry: CTA 128(m) x 128(n), 256 thr, 8 warps (4m x 2n),
// warp tile 32 x 64, K-chunk 64, 3-stage cp.async multistage, 2 CTAs/SM.
// ---------------------------------------------------------------------------
#define OFF_W   16384
#define STAGE_B 32768
#define SCAN_SMEM (9 * 128 * 4)
#define SMEM_FUSED (1024 + 3 * STAGE_B + SCAN_SMEM)
#define SMEM_GEMM  (1024 + 3 * STAGE_B)

// 1-term fp16 compute of one K64 chunk for warp tile 32x64.
__device__ __forceinline__ void chunk_compute(uint32_t sb, int warp_m, int warp_n,
                                              int lane, float acc[2][8][4])
{
    const uint32_t sA = sb, sW = sb + OFF_W;
    #pragma unroll
    for (int ks = 0; ks < 4; ++ks) {
        const int akb = ks * 32 + ((lane & 16) ? 16 : 0);
        uint32_t a[2][4];
        #pragma unroll
        for (int mt = 0; mt < 2; ++mt) {
            const int row = warp_m + mt * 16 + (lane & 15);
            ldsm4(a[mt], sA + SW128((uint32_t)(row * 128 + akb)));
        }
        const int bkb = ks * 32 + ((lane & 8) ? 16 : 0);
        uint32_t w[4][4];
        #pragma unroll
        for (int nt2 = 0; nt2 < 4; ++nt2) {
            const int brow = warp_n + nt2 * 16 + (lane & 7) + ((lane & 16) ? 8 : 0);
            ldsm4(w[nt2], sW + SW128((uint32_t)(brow * 128 + bkb)));
        }
        #pragma unroll
        for (int nt2 = 0; nt2 < 4; ++nt2)
            #pragma unroll
            for (int mt = 0; mt < 2; ++mt) {
                mma16816(acc[mt][nt2 * 2 + 0], a[mt], w[nt2][0], w[nt2][1]);
                mma16816(acc[mt][nt2 * 2 + 1], a[mt], w[nt2][2], w[nt2][3]);
            }
    }
}

__device__ __forceinline__ void acc_zero(float acc[2][8][4]) {
    #pragma unroll
    for (int a = 0; a < 2; ++a)
        #pragma unroll
        for (int b = 0; b < 8; ++b)
            #pragma unroll
            for (int c = 0; c < 4; ++c) acc[a][b][c] = 0.0f;
}

// Write acc tile (fp16) into a 128x128 ring slot (row = t_local, col = h_local).
__device__ __forceinline__ void acc_to_ring(float acc[2][8][4], __half* ring,
                                            int warp_m, int warp_n, int lane)
{
    #pragma unroll
    for (int mt = 0; mt < 2; ++mt) {
        #pragma unroll
        for (int half = 0; half < 2; ++half) {
            const int tl = warp_m + mt * 16 + (lane >> 2) + half * 8;
            __half* rowp = ring + tl * 128 + warp_n;
            #pragma unroll
            for (int nt = 0; nt < 8; ++nt) {
                const int n = nt * 8 + (lane & 3) * 2;
                float v0 = half ? acc[mt][nt][2] : acc[mt][nt][0];
                float v1 = half ? acc[mt][nt][3] : acc[mt][nt][1];
                *(__half2*)(rowp + n) = __floats2half2_rn(v0, v1);
            }
        }
    }
}

// ---------------------------------------------------------------------------
// Fused GEMM-1 + scan. Grid (4 n-tiles, 64 b), 256 thr, 2 CTAs/SM = 1 wave.
// ---------------------------------------------------------------------------
__global__ __launch_bounds__(256, 2)
void fused_gemm1_scan_kernel(const float* __restrict__ b1,
                             const float* __restrict__ tau1,
                             const float* __restrict__ b2,
                             const float* __restrict__ tau2)
{
    extern __shared__ __align__(16) char smraw[];
    char* smem = smraw + ((1024 - (smem_u32(smraw) & 1023)) & 1023);
    const uint32_t sbase = smem_u32(smem);
    float* s_scan = (float*)(smem + 3 * STAGE_B);   // [9][128]

    const int tid    = threadIdx.x;
    const int wid    = tid >> 5;
    const int lane   = tid & 31;
    const int warp_m = (wid & 3) * 32;
    const int warp_n = (wid >> 2) * 64;

    const int n0  = blockIdx.x * 128;
    const int b   = blockIdx.y;
    const int cta = b * 4 + blockIdx.x;

    __half* ring1 = g_ring + (size_t)(cta * 2 + 0) * (128 * 128);
    __half* ring2 = g_ring + (size_t)(cta * 2 + 1) * (128 * 128);

    if (tid < 128) {
        const int h = n0 + tid;
        const float a1 = 1.0f / (1.0f + __expf(-tau1[h]));
        const float a2 = 1.0f / (1.0f + __expf(-tau2[h]));
        s_scan[0 * 128 + tid] = a1;
        s_scan[1 * 128 + tid] = (1.0f - a1);
        s_scan[2 * 128 + tid] = b1[h];
        s_scan[3 * 128 + tid] = a2;
        s_scan[4 * 128 + tid] = (1.0f - a2);
        s_scan[5 * 128 + tid] = b2[h];
        s_scan[6 * 128 + tid] = 0.0f;
        s_scan[7 * 128 + tid] = 0.0f;
        s_scan[8 * 128 + tid] = 0.0f;
    }

    auto issue_chunk = [&](int cc) {
        const uint32_t sb = sbase + (cc % 3) * STAGE_B;
        const int tc = cc >> 3;
        const int p  = cc & 7;
        const __half* w = (p >= 4) ? g_w2 : g_w1;
        const int kx = (p & 3) * 64 + ((p >= 4) ? HALF_ : 0);
        const int kw = (p & 3) * 64;
        const int m0 = b * T_ + tc * 128;
        cp_tile64<128>(sb,         g_x16, D_,    m0, kx, tid);
        cp_tile64<128>(sb + OFF_W, w,     HALF_, n0, kw, tid);
        CP_COMMIT();
    };

    float acc[2][8][4];
    acc_zero(acc);

    issue_chunk(0);
    issue_chunk(1);

    #pragma unroll 1
    for (int cc = 0; cc < 64; ++cc) {
        if (cc < 63) { CP_WAIT1(); } else { CP_WAIT0(); }
        __syncthreads();
        if (cc + 2 < 64) issue_chunk(cc + 2);

        chunk_compute(sbase + (cc % 3) * STAGE_B, warp_m, warp_n, lane, acc);

        const int p = cc & 7;
        if (p == 3) {
            acc_to_ring(acc, ring1, warp_m, warp_n, lane);
            acc_zero(acc);
        } else if (p == 7) {
            acc_to_ring(acc, ring2, warp_m, warp_n, lane);
            acc_zero(acc);
            __syncthreads();

            if (tid < 128) {
                const int tc = cc >> 3;
                const float a1  = s_scan[0 * 128 + tid];
                const float c1  = s_scan[1 * 128 + tid];
                const float bb1 = s_scan[2 * 128 + tid];
                const float a2  = s_scan[3 * 128 + tid];
                const float c2  = s_scan[4 * 128 + tid];
                const float bb2 = s_scan[5 * 128 + tid];
                float d1v = s_scan[6 * 128 + tid];
                float d2v = s_scan[7 * 128 + tid];
                float mv  = s_scan[8 * 128 + tid];
                #pragma unroll 1
                for (int tb = 0; tb < 128; tb += 8) {
                    __half i1[8], i2[8];
                    #pragma unroll
                    for (int u = 0; u < 8; ++u) {
                        i1[u] = ring1[(tb + u) * 128 + tid];
                        i2[u] = ring2[(tb + u) * 128 + tid];
                    }
                    #pragma unroll
                    for (int u = 0; u < 8; ++u) {
                        d1v = a1 * d1v + c1 * (__half2float(i1[u]) + bb1);
                        d2v = a2 * d2v + c2 * (__half2float(i2[u]) + bb2);
                        mv  = 0.8f * mv + 0.2f * (d1v + d2v);
                        const int tg = tc * 128 + tb + u;
                        g_m16[((size_t)tg * B_ + b) * H_ + n0 + tid] =
                            __float2half_rn(mv);
                    }
                }
                s_scan[6 * 128 + tid] = d1v;
                s_scan[7 * 128 + tid] = d2v;
                s_scan[8 * 128 + tid] = mv;
            }
        }
    }
}

// ---------------------------------------------------------------------------
// GEMM-2 (persistent): out = sigmoid(mems @ wo^T + bo). Grid 256 CTAs = ONE
// wave at 2 CTAs/SM; each CTA runs TWO m-tiles through one continuous
// 16-chunk pipeline (epilogues at chunk 7 and 15). wo K-tiles are L2-hot
// for the second m-tile.
// ---------------------------------------------------------------------------
__global__ __launch_bounds__(256, 2)
void hmma_gemm2_kernel(const float* __restrict__ bo, float* __restrict__ out)
{
    extern __shared__ __align__(16) char smraw[];
    char* smem = smraw + ((1024 - (smem_u32(smraw) & 1023)) & 1023);
    const uint32_t sbase = smem_u32(smem);

    const int tid    = threadIdx.x;
    const int wid    = tid >> 5;
    const int lane   = tid & 31;
    const int warp_m = (wid & 3) * 32;
    const int warp_n = (wid >> 2) * 64;

    const int m0a = blockIdx.x * 128;
    const int m0b = (blockIdx.x + 256) * 128;

    auto issue_chunk = [&](int c) {
        const uint32_t sb = sbase + (c % 3) * STAGE_B;
        const int m0 = (c >= 8) ? m0b : m0a;
        const int k1 = (c & 7) * 64;
        cp_tile64<128>(sb,         g_m16, H_, m0, k1, tid);
        cp_tile64<128>(sb + OFF_W, g_wo,  H_, 0,  k1, tid);
        CP_COMMIT();
    };

    auto epilogue = [&](float acc[2][8][4], int m0) {
        #pragma unroll
        for (int mt = 0; mt < 2; ++mt) {
            #pragma unroll
            for (int half = 0; half < 2; ++half) {
                const int m = m0 + warp_m + mt * 16 + (lane >> 2) + half * 8;
                const int t = m >> 6;           // / B_
                const int b = m & (B_ - 1);
                float* rowp = out + (size_t)b * (T_ * O_) + (size_t)t * O_ + warp_n;
                #pragma unroll
                for (int nt = 0; nt < 8; ++nt) {
                    const int n = nt * 8 + (lane & 3) * 2;
                    float v0 = half ? acc[mt][nt][2] : acc[mt][nt][0];
                    float v1 = half ? acc[mt][nt][3] : acc[mt][nt][1];
                    v0 += bo[warp_n + n];
                    v1 += bo[warp_n + n + 1];
                    v0 = 1.0f / (1.0f + __expf(-v0));
                    v1 = 1.0f / (1.0f + __expf(-v1));
                    *(float2*)(rowp + n) = make_float2(v0, v1);
                }
            }
        }
    };

    float acc[2][8][4];
    acc_zero(acc);

    issue_chunk(0);
    issue_chunk(1);

    #pragma unroll 1
    for (int c = 0; c < 16; ++c) {
        if (c < 15) { CP_WAIT1(); } else { CP_WAIT0(); }
        __syncthreads();
        if (c + 2 < 16) issue_chunk(c + 2);

        chunk_compute(sbase + (c % 3) * STAGE_B, warp_m, warp_n, lane, acc);

        if (c == 7) {
            epilogue(acc, m0a);
            acc_zero(acc);
        } else if (c == 15) {
            epilogue(acc, m0b);
        }
    }
}

// ---------------------------------------------------------------------------
extern "C" void kernel_launch(void* const* d_in, const int* in_sizes, int n_in,
                              void* d_out, int out_size)
{
    const float* x    = (const float*)d_in[0];
    const float* w1   = (const float*)d_in[1];
    const float* b1   = (const float*)d_in[2];
    const float* tau1 = (const float*)d_in[3];
    const float* w2   = (const float*)d_in[4];
    const float* b2   = (const float*)d_in[5];
    const float* tau2 = (const float*)d_in[6];
    const float* wo   = (const float*)d_in[7];
    const float* bo   = (const float*)d_in[8];
    float* out = (float*)d_out;

    cudaFuncSetAttribute(fused_gemm1_scan_kernel,
                         cudaFuncAttributeMaxDynamicSharedMemorySize, SMEM_FUSED);
    cudaFuncSetAttribute(hmma_gemm2_kernel,
                         cudaFuncAttributeMaxDynamicSharedMemorySize, SMEM_GEMM);

    split_all_kernel<<<2048, 256>>>(x, w1, w2, wo);

    dim3 g1(H_ / 128, B_);                // (4, 64) = 256 CTAs, one wave
    fused_gemm1_scan_kernel<<<g1, 256, SMEM_FUSED>>>(b1, tau1, b2, tau2);

    hmma_gemm2_kernel<<<256, 256, SMEM_GEMM>>>(bo, out);
}